// round 2
// baseline (speedup 1.0000x reference)
#include <cuda_runtime.h>
#include <math.h>
#include <stdint.h>

// ---------------- problem constants ----------------
#define N_NODES 50000
#define NUM_FEA 213
#define HID1 16
#define HEAD1 12
#define CH1 (HID1*HEAD1)   // 192
#define HID2 8
#define HEAD2 8
#define CH2 (HID2*HEAD2)   // 64
#define E_EDGES 800000
#define E_TOT (E_EDGES + N_NODES)   // 850000 (with self loops)

// ---------------- device scratch (no allocs allowed) ----------------
static __device__ float g_h1[N_NODES*CH1];     // features @ W1
static __device__ float g_x1[N_NODES*CH1];     // elu(gat1 out)
static __device__ float g_h2[N_NODES*CH2];     // x1 @ W2
static __device__ float g_as1[N_NODES*HEAD1];
static __device__ float g_ad1[N_NODES*HEAD1];
static __device__ float g_as2[N_NODES*HEAD2];
static __device__ float g_ad2[N_NODES*HEAD2];
static __device__ int   g_deg[N_NODES];
static __device__ int   g_cur[N_NODES];
static __device__ int   g_tmp[N_NODES];
static __device__ int   g_offs[N_NODES+1];
static __device__ int   g_bsum[64];
static __device__ int   g_srcs[E_TOT];

// ---------------- CSR build ----------------
__global__ void zero_kernel(int n)
{
    int i = blockIdx.x*blockDim.x + threadIdx.x;
    if (i < n) { g_deg[i] = 0; g_cur[i] = 0; }
}

__global__ void count_kernel(const int* __restrict__ dstE, int E, int n)
{
    int i = blockIdx.x*blockDim.x + threadIdx.x;
    int tot = E + n;
    if (i >= tot) return;
    int d = (i < E) ? dstE[i] : (i - E);   // self loops appended
    atomicAdd(&g_deg[d], 1);
}

__global__ void scan1_kernel(int n)
{
    __shared__ int sh[1024];
    int t = threadIdx.x;
    int i = blockIdx.x*1024 + t;
    sh[t] = (i < n) ? g_deg[i] : 0;
    __syncthreads();
    #pragma unroll
    for (int off = 1; off < 1024; off <<= 1) {
        int v = 0;
        if (t >= off) v = sh[t-off];
        __syncthreads();
        sh[t] += v;
        __syncthreads();
    }
    if (i < n) g_tmp[i] = sh[t];
    if (t == 1023) g_bsum[blockIdx.x] = sh[1023];
}

__global__ void scan2_kernel(int nb)   // exclusive scan of <=64 block sums
{
    __shared__ int sh[64];
    int t = threadIdx.x;
    int mine = (t < nb) ? g_bsum[t] : 0;
    sh[t] = mine;
    __syncthreads();
    #pragma unroll
    for (int off = 1; off < 64; off <<= 1) {
        int v = (t >= off) ? sh[t-off] : 0;
        __syncthreads();
        sh[t] += v;
        __syncthreads();
    }
    if (t < nb) g_bsum[t] = sh[t] - mine;
}

__global__ void scan3_kernel(int n)
{
    int i = blockIdx.x*blockDim.x + threadIdx.x;
    if (i < n) g_offs[i+1] = g_tmp[i] + g_bsum[i >> 10];
    if (i == 0) g_offs[0] = 0;
}

__global__ void scatter_kernel(const int* __restrict__ srcE,
                               const int* __restrict__ dstE, int E, int n)
{
    int i = blockIdx.x*blockDim.x + threadIdx.x;
    int tot = E + n;
    if (i >= tot) return;
    int s, d;
    if (i < E) { s = srcE[i]; d = dstE[i]; }
    else       { s = d = i - E; }
    int pos = g_offs[d] + atomicAdd(&g_cur[d], 1);
    g_srcs[pos] = s;
}

// ---------------- tensor-core 3xTF32 GEMM: C[M,N] = A[M,K]*B[K,N] -----------
// BM=64, BN = full N (192 or 64), BK=16, 256 threads = 8 warps (4x2 warp grid).
// 3xTF32 split: a = hi + lo, D += hi_a*hi_b + hi_a*lo_b + lo_a*hi_b (fp32-level acc).
__device__ __forceinline__ uint32_t f2tf32(float x)
{
    uint32_t u;
    asm("cvt.rna.tf32.f32 %0, %1;" : "=r"(u) : "f"(x));
    return u;
}

__device__ __forceinline__ void mma_tf32(float* d, const uint32_t* a, const uint32_t* b)
{
    asm volatile("mma.sync.aligned.m16n8k8.row.col.f32.tf32.tf32.f32 "
                 "{%0,%1,%2,%3}, {%4,%5,%6,%7}, {%8,%9}, {%0,%1,%2,%3};"
                 : "+f"(d[0]), "+f"(d[1]), "+f"(d[2]), "+f"(d[3])
                 : "r"(a[0]), "r"(a[1]), "r"(a[2]), "r"(a[3]),
                   "r"(b[0]), "r"(b[1]));
}

template<int BN>
__global__ __launch_bounds__(256)
void gemm_tc_kernel(const float* __restrict__ A,
                    const float* __restrict__ B,
                    float* __restrict__ C,
                    int M, int K)
{
    const int N = BN;                  // full output width per block
    const int BM = 64, BK = 16;
    const int WN = BN/2;               // per-warp col span
    const int NT = WN/8;               // n-tiles per warp

    __shared__ uint32_t sAhi[BM][BK+1];
    __shared__ uint32_t sAlo[BM][BK+1];
    __shared__ uint32_t sBhi[BK][BN+4];
    __shared__ uint32_t sBlo[BK][BN+4];

    int tx   = threadIdx.x;
    int lane = tx & 31;
    int wid  = tx >> 5;                // 0..7
    int wr   = wid & 3;                // m-tile (16 rows)
    int wc   = wid >> 2;               // col half

    int row0 = blockIdx.x * BM;

    float acc[NT][4];
    #pragma unroll
    for (int nt = 0; nt < NT; nt++)
        #pragma unroll
        for (int j = 0; j < 4; j++) acc[nt][j] = 0.f;

    for (int k0 = 0; k0 < K; k0 += BK) {
        // load+convert A tile (BM x BK)
        #pragma unroll
        for (int idx = tx; idx < BM*BK; idx += 256) {
            int r = idx >> 4, kk = idx & 15;
            int gr = row0 + r, gk = k0 + kk;
            float v = (gr < M && gk < K) ? A[(long)gr*K + gk] : 0.f;
            uint32_t hi = f2tf32(v);
            sAhi[r][kk] = hi;
            sAlo[r][kk] = f2tf32(v - __uint_as_float(hi));
        }
        // load+convert B tile (BK x BN)
        #pragma unroll
        for (int idx = tx; idx < BK*BN; idx += 256) {
            int kk = idx / BN, c = idx % BN;
            int gk = k0 + kk;
            float v = (gk < K) ? B[(long)gk*N + c] : 0.f;
            uint32_t hi = f2tf32(v);
            sBhi[kk][c] = hi;
            sBlo[kk][c] = f2tf32(v - __uint_as_float(hi));
        }
        __syncthreads();

        #pragma unroll
        for (int ks = 0; ks < 2; ks++) {
            int kb = ks*8;
            int ar = wr*16 + (lane>>2);
            int ak = kb + (lane&3);
            uint32_t ahi[4], alo[4];
            ahi[0] = sAhi[ar  ][ak  ]; ahi[1] = sAhi[ar+8][ak  ];
            ahi[2] = sAhi[ar  ][ak+4]; ahi[3] = sAhi[ar+8][ak+4];
            alo[0] = sAlo[ar  ][ak  ]; alo[1] = sAlo[ar+8][ak  ];
            alo[2] = sAlo[ar  ][ak+4]; alo[3] = sAlo[ar+8][ak+4];
            #pragma unroll
            for (int nt = 0; nt < NT; nt++) {
                int nc = wc*WN + nt*8 + (lane>>2);
                int bk0 = kb + (lane&3);
                uint32_t bhi[2], blo[2];
                bhi[0] = sBhi[bk0  ][nc]; bhi[1] = sBhi[bk0+4][nc];
                blo[0] = sBlo[bk0  ][nc]; blo[1] = sBlo[bk0+4][nc];
                mma_tf32(acc[nt], ahi, bhi);
                mma_tf32(acc[nt], ahi, blo);
                mma_tf32(acc[nt], alo, bhi);
            }
        }
        __syncthreads();
    }

    // epilogue
    int gr0 = row0 + wr*16 + (lane>>2);
    int gr1 = gr0 + 8;
    #pragma unroll
    for (int nt = 0; nt < NT; nt++) {
        int gc = wc*WN + nt*8 + (lane&3)*2;
        if (gr0 < M)
            *(float2*)&C[(long)gr0*N + gc] = make_float2(acc[nt][0], acc[nt][1]);
        if (gr1 < M)
            *(float2*)&C[(long)gr1*N + gc] = make_float2(acc[nt][2], acc[nt][3]);
    }
}

// ---------------- attention scores a_s[n,h], a_d[n,h] ----------------
template<int H, int C>
__global__ void attn_kernel(const float* __restrict__ h,
                            const float* __restrict__ att_s,
                            const float* __restrict__ att_d,
                            float* __restrict__ as_out,
                            float* __restrict__ ad_out, int N)
{
    int t = blockIdx.x*blockDim.x + threadIdx.x;
    if (t >= N*H) return;
    int hh = t % H;
    const float* hp = h + (long)t * C;       // t = n*H + hh; h row-major [N, H*C]
    const float* sp = att_s + hh*C;
    const float* dp = att_d + hh*C;
    float s = 0.f, d = 0.f;
    #pragma unroll
    for (int c = 0; c < C; c += 4) {
        float4 hv = *(const float4*)&hp[c];
        float4 sv = *(const float4*)&sp[c];
        float4 dv = *(const float4*)&dp[c];
        s = fmaf(hv.x,sv.x, fmaf(hv.y,sv.y, fmaf(hv.z,sv.z, fmaf(hv.w,sv.w, s))));
        d = fmaf(hv.x,dv.x, fmaf(hv.y,dv.y, fmaf(hv.z,dv.z, fmaf(hv.w,dv.w, d))));
    }
    as_out[t] = s;
    ad_out[t] = d;
}

// ---------------- per-dst-node softmax aggregation (one warp / node) ----------
template<int H, int C>
__global__ void agg_kernel(const float* __restrict__ h,
                           const float* __restrict__ as_in,
                           const float* __restrict__ ad_in,
                           const float* __restrict__ bias,
                           float* __restrict__ out, int N)
{
    constexpr int CH = H*C;
    constexpr int J  = CH/32;
    int warp = (blockIdx.x*blockDim.x + threadIdx.x) >> 5;
    int lane = threadIdx.x & 31;
    if (warp >= N) return;
    const int v = warp;

    float adv = (lane < H) ? ad_in[v*H + lane] : 0.f;
    int b = g_offs[v], e = g_offs[v+1];

    float den = 0.f;
    float acc[J];
    #pragma unroll
    for (int j = 0; j < J; j++) acc[j] = 0.f;

    for (int i = b; i < e; i++) {
        int s = g_srcs[i];
        float ex = 0.f;
        if (lane < H) {
            float ev = as_in[s*H + lane] + adv;
            ev = (ev > 0.f) ? ev : 0.2f*ev;      // leaky_relu
            ex = __expf(ev);                      // no max-shift: same alpha exactly
            den += ex;
        }
        const float* hp = h + (long)s*CH;
        #pragma unroll
        for (int j = 0; j < J; j++) {
            int ch = lane + 32*j;
            float exh = __shfl_sync(0xffffffffu, ex, ch / C);
            acc[j] = fmaf(exh, hp[ch], acc[j]);
        }
    }
    #pragma unroll
    for (int j = 0; j < J; j++) {
        int ch = lane + 32*j;
        float dh = __shfl_sync(0xffffffffu, den, ch / C);
        float o = acc[j]/dh + bias[ch];
        o = (o > 0.f) ? o : expm1f(o);           // elu
        out[(long)v*CH + ch] = o;
    }
}

// ---------------- pair head: sigmoid(concat(x[n1],x[n2]) @ linW + linb) ------
__global__ void pair_kernel(const float* __restrict__ x2,
                            const int* __restrict__ n1,
                            const int* __restrict__ n2,
                            const float* __restrict__ linW,
                            const float* __restrict__ linb,
                            float* __restrict__ y, int P)
{
    int p = blockIdx.x*blockDim.x + threadIdx.x;
    if (p >= P) return;
    const float* a  = x2 + (long)n1[p]*CH2;
    const float* bb = x2 + (long)n2[p]*CH2;
    float y0 = linb[0], y1 = linb[1];
    #pragma unroll
    for (int j = 0; j < CH2; j++) {
        float v = a[j];
        y0 = fmaf(v, linW[j*2],   y0);
        y1 = fmaf(v, linW[j*2+1], y1);
    }
    #pragma unroll
    for (int j = 0; j < CH2; j++) {
        float v = bb[j];
        y0 = fmaf(v, linW[(CH2+j)*2],   y0);
        y1 = fmaf(v, linW[(CH2+j)*2+1], y1);
    }
    y[p*2]   = 1.f/(1.f + __expf(-y0));
    y[p*2+1] = 1.f/(1.f + __expf(-y1));
}

// ---------------- launch ----------------
extern "C" void kernel_launch(void* const* d_in, const int* in_sizes, int n_in,
                              void* d_out, int out_size)
{
    const float* features = (const float*)d_in[0];
    const int*   eidx     = (const int*)  d_in[1];
    const int*   n1idx    = (const int*)  d_in[2];
    const int*   n2idx    = (const int*)  d_in[3];
    const float* W1       = (const float*)d_in[4];
    const float* attS1    = (const float*)d_in[5];
    const float* attD1    = (const float*)d_in[6];
    const float* b1       = (const float*)d_in[7];
    const float* W2       = (const float*)d_in[8];
    const float* attS2    = (const float*)d_in[9];
    const float* attD2    = (const float*)d_in[10];
    const float* b2       = (const float*)d_in[11];
    const float* linW     = (const float*)d_in[12];
    const float* linb     = (const float*)d_in[13];

    const int N = N_NODES;
    const int E = in_sizes[1] / 2;
    const int P = in_sizes[2];
    const int etot = E + N;
    const int* srcE = eidx;
    const int* dstE = eidx + E;

    float* y_out  = (float*)d_out;          // [P,2]
    float* x2_out = y_out + (long)P*2;      // [N,64]

    float *p_h1, *p_x1, *p_h2, *p_as1, *p_ad1, *p_as2, *p_ad2;
    cudaGetSymbolAddress((void**)&p_h1,  g_h1);
    cudaGetSymbolAddress((void**)&p_x1,  g_x1);
    cudaGetSymbolAddress((void**)&p_h2,  g_h2);
    cudaGetSymbolAddress((void**)&p_as1, g_as1);
    cudaGetSymbolAddress((void**)&p_ad1, g_ad1);
    cudaGetSymbolAddress((void**)&p_as2, g_as2);
    cudaGetSymbolAddress((void**)&p_ad2, g_ad2);

    // ---- CSR build interleaved with GEMM1 (gemm1 placed 4th for ncu -s) ----
    zero_kernel<<<(N+255)/256, 256>>>(N);
    count_kernel<<<(etot+255)/256, 256>>>(dstE, E, N);
    int nb = (N + 1023) / 1024;
    scan1_kernel<<<nb, 1024>>>(N);
    gemm_tc_kernel<CH1><<<(N + 63)/64, 256>>>(features, W1, p_h1, N, NUM_FEA);
    scan2_kernel<<<1, 64>>>(nb);
    scan3_kernel<<<(N+255)/256, 256>>>(N);
    scatter_kernel<<<(etot+255)/256, 256>>>(srcE, dstE, E, N);

    // ---- layer 1 ----
    attn_kernel<HEAD1, HID1><<<(N*HEAD1 + 255)/256, 256>>>(p_h1, attS1, attD1, p_as1, p_ad1, N);
    agg_kernel<HEAD1, HID1><<<(N*32 + 255)/256, 256>>>(p_h1, p_as1, p_ad1, b1, p_x1, N);

    // ---- layer 2 ----
    gemm_tc_kernel<CH2><<<(N + 63)/64, 256>>>(p_x1, W2, p_h2, N, CH1);
    attn_kernel<HEAD2, HID2><<<(N*HEAD2 + 255)/256, 256>>>(p_h2, attS2, attD2, p_as2, p_ad2, N);
    agg_kernel<HEAD2, HID2><<<(N*32 + 255)/256, 256>>>(p_h2, p_as2, p_ad2, b2, x2_out, N);

    // ---- pair head ----
    pair_kernel<<<(P+255)/256, 256>>>(x2_out, n1idx, n2idx, linW, linb, y_out, P);
}

// round 3
// speedup vs baseline: 1.2077x; 1.2077x over previous
#include <cuda_runtime.h>
#include <math.h>
#include <stdint.h>

// ---------------- problem constants ----------------
#define N_NODES 50000
#define NUM_FEA 213
#define HID1 16
#define HEAD1 12
#define CH1 (HID1*HEAD1)   // 192
#define HID2 8
#define HEAD2 8
#define CH2 (HID2*HEAD2)   // 64
#define E_EDGES 800000
#define E_TOT (E_EDGES + N_NODES)   // 850000 (with self loops)

// ---------------- device scratch (no allocs allowed) ----------------
static __device__ float g_h1[N_NODES*CH1];
static __device__ float g_x1[N_NODES*CH1];
static __device__ float g_h2[N_NODES*CH2];
static __device__ float g_as1[N_NODES*HEAD1];
static __device__ float g_ad1[N_NODES*HEAD1];
static __device__ float g_as2[N_NODES*HEAD2];
static __device__ float g_ad2[N_NODES*HEAD2];
static __device__ int   g_deg[N_NODES];
static __device__ int   g_cur[N_NODES];
static __device__ int   g_tmp[N_NODES];
static __device__ int   g_offs[N_NODES+1];
static __device__ int   g_bsum[64];
static __device__ int   g_srcs[E_TOT];

// ---------------- CSR build ----------------
__global__ void zero_kernel(int n)
{
    int i = blockIdx.x*blockDim.x + threadIdx.x;
    if (i < n) { g_deg[i] = 0; g_cur[i] = 0; }
}

__global__ void count_kernel(const int* __restrict__ dstE, int E, int n)
{
    int i = blockIdx.x*blockDim.x + threadIdx.x;
    int tot = E + n;
    if (i >= tot) return;
    int d = (i < E) ? dstE[i] : (i - E);
    atomicAdd(&g_deg[d], 1);
}

__global__ void scan1_kernel(int n)
{
    __shared__ int sh[1024];
    int t = threadIdx.x;
    int i = blockIdx.x*1024 + t;
    sh[t] = (i < n) ? g_deg[i] : 0;
    __syncthreads();
    #pragma unroll
    for (int off = 1; off < 1024; off <<= 1) {
        int v = 0;
        if (t >= off) v = sh[t-off];
        __syncthreads();
        sh[t] += v;
        __syncthreads();
    }
    if (i < n) g_tmp[i] = sh[t];
    if (t == 1023) g_bsum[blockIdx.x] = sh[1023];
}

__global__ void scan2_kernel(int nb)
{
    __shared__ int sh[64];
    int t = threadIdx.x;
    int mine = (t < nb) ? g_bsum[t] : 0;
    sh[t] = mine;
    __syncthreads();
    #pragma unroll
    for (int off = 1; off < 64; off <<= 1) {
        int v = (t >= off) ? sh[t-off] : 0;
        __syncthreads();
        sh[t] += v;
        __syncthreads();
    }
    if (t < nb) g_bsum[t] = sh[t] - mine;
}

__global__ void scan3_kernel(int n)
{
    int i = blockIdx.x*blockDim.x + threadIdx.x;
    if (i < n) g_offs[i+1] = g_tmp[i] + g_bsum[i >> 10];
    if (i == 0) g_offs[0] = 0;
}

__global__ void scatter_kernel(const int* __restrict__ srcE,
                               const int* __restrict__ dstE, int E, int n)
{
    int i = blockIdx.x*blockDim.x + threadIdx.x;
    int tot = E + n;
    if (i >= tot) return;
    int s, d;
    if (i < E) { s = srcE[i]; d = dstE[i]; }
    else       { s = d = i - E; }
    int pos = g_offs[d] + atomicAdd(&g_cur[d], 1);
    g_srcs[pos] = s;
}

// ---------------- tensor-core 3xTF32 GEMM, fragment-major smem -------------
__device__ __forceinline__ uint32_t f2tf32(float x)
{
    uint32_t u;
    asm("cvt.rna.tf32.f32 %0, %1;" : "=r"(u) : "f"(x));
    return u;
}

__device__ __forceinline__ void mma_tf32(float* d, const uint32_t* a, const uint32_t* b)
{
    asm volatile("mma.sync.aligned.m16n8k8.row.col.f32.tf32.tf32.f32 "
                 "{%0,%1,%2,%3}, {%4,%5,%6,%7}, {%8,%9}, {%0,%1,%2,%3};"
                 : "+f"(d[0]), "+f"(d[1]), "+f"(d[2]), "+f"(d[3])
                 : "r"(a[0]), "r"(a[1]), "r"(a[2]), "r"(a[3]),
                   "r"(b[0]), "r"(b[1]));
}

// BM=64, BK=16, 256 threads = 8 warps (4 row-tiles x 2 col-halves).
// smem A: [g(4)][ks(2)][lane(32)][ahi0..3, alo0..3]  -> one LDS.128 per frag
// smem B: [ks(2)][c(BN)][k4(4)][bhi_k, bhi_k4, blo_k, blo_k4] -> one LDS.128
template<int BN>
__global__ __launch_bounds__(256, 2)
void gemm_tc_kernel(const float* __restrict__ A,
                    const float* __restrict__ B,
                    float* __restrict__ C,
                    int M, int N, int K)
{
    constexpr int BM = 64, BK = 16;
    constexpr int WN = BN/2;
    constexpr int NT = WN/8;

    __shared__ uint32_t sA[4*2*32*8];        // 2048 u32 = 8KB
    __shared__ uint32_t sB[2*BN*4*4];        // BN=96: 3072 u32 = 12KB

    int tx   = threadIdx.x;
    int lane = tx & 31;
    int wid  = tx >> 5;
    int wr   = wid & 3;
    int wc   = wid >> 2;

    int row0 = blockIdx.x * BM;
    int col0 = blockIdx.y * BN;

    float acc[NT][4];
    #pragma unroll
    for (int nt = 0; nt < NT; nt++)
        #pragma unroll
        for (int j = 0; j < 4; j++) acc[nt][j] = 0.f;

    int nk = (K + BK - 1) / BK;
    for (int kt = 0; kt < nk; kt++) {
        int k0 = kt * BK;
        // ---- stage A tile (64x16) in fragment-major layout ----
        #pragma unroll
        for (int i = 0; i < (BM*BK)/256; i++) {
            int idx = tx + i*256;
            int r = idx >> 4, kk = idx & 15;
            int gr = row0 + r, gk = k0 + kk;
            float v = (gr < M && gk < K) ? A[(long)gr*K + gk] : 0.f;
            uint32_t hi = f2tf32(v);
            uint32_t lo = f2tf32(v - __uint_as_float(hi));
            int g = r >> 4, rr = r & 15, ks = kk >> 3, cc = kk & 7;
            int ln  = (rr & 7)*4 + (cc & 3);
            int val = (rr >> 3) + 2*(cc >> 2);
            int base = ((g*2 + ks)*32 + ln)*8;
            sA[base + val]     = hi;
            sA[base + 4 + val] = lo;
        }
        // ---- stage B tile (16xBN) in fragment-major layout ----
        #pragma unroll
        for (int i = 0; i < (BK*BN)/256; i++) {
            int idx = tx + i*256;
            int kk = idx / BN, c = idx % BN;
            int gk = k0 + kk;
            float v = (gk < K) ? B[(long)gk*N + col0 + c] : 0.f;
            uint32_t hi = f2tf32(v);
            uint32_t lo = f2tf32(v - __uint_as_float(hi));
            int ks = kk >> 3, cc = kk & 7;
            int k4 = cc & 3, kh = cc >> 2;
            int base = ((ks*BN + c)*4 + k4)*4;
            sB[base + kh]     = hi;
            sB[base + 2 + kh] = lo;
        }
        __syncthreads();

        #pragma unroll
        for (int ks = 0; ks < 2; ks++) {
            uint4 a0 = *(const uint4*)&sA[((wr*2 + ks)*32 + lane)*8];
            uint4 a1 = *(const uint4*)&sA[((wr*2 + ks)*32 + lane)*8 + 4];
            uint32_t ahi[4] = {a0.x, a0.y, a0.z, a0.w};
            uint32_t alo[4] = {a1.x, a1.y, a1.z, a1.w};
            #pragma unroll
            for (int nt = 0; nt < NT; nt++) {
                int nc = wc*WN + nt*8 + (lane >> 2);
                uint4 b4 = *(const uint4*)&sB[((ks*BN + nc)*4 + (lane & 3))*4];
                uint32_t bhi[2] = {b4.x, b4.y};
                uint32_t blo[2] = {b4.z, b4.w};
                mma_tf32(acc[nt], ahi, bhi);
                mma_tf32(acc[nt], ahi, blo);
                mma_tf32(acc[nt], alo, bhi);
            }
        }
        __syncthreads();
    }

    int gr0 = row0 + wr*16 + (lane >> 2);
    int gr1 = gr0 + 8;
    #pragma unroll
    for (int nt = 0; nt < NT; nt++) {
        int gc = col0 + wc*WN + nt*8 + (lane & 3)*2;
        if (gr0 < M)
            *(float2*)&C[(long)gr0*N + gc] = make_float2(acc[nt][0], acc[nt][1]);
        if (gr1 < M)
            *(float2*)&C[(long)gr1*N + gc] = make_float2(acc[nt][2], acc[nt][3]);
    }
}

// ---------------- attention scores ----------------
template<int H, int C>
__global__ void attn_kernel(const float* __restrict__ h,
                            const float* __restrict__ att_s,
                            const float* __restrict__ att_d,
                            float* __restrict__ as_out,
                            float* __restrict__ ad_out, int N)
{
    int t = blockIdx.x*blockDim.x + threadIdx.x;
    if (t >= N*H) return;
    int hh = t % H;
    const float* hp = h + (long)t * C;
    const float* sp = att_s + hh*C;
    const float* dp = att_d + hh*C;
    float s = 0.f, d = 0.f;
    #pragma unroll
    for (int c = 0; c < C; c += 4) {
        float4 hv = *(const float4*)&hp[c];
        float4 sv = *(const float4*)&sp[c];
        float4 dv = *(const float4*)&dp[c];
        s = fmaf(hv.x,sv.x, fmaf(hv.y,sv.y, fmaf(hv.z,sv.z, fmaf(hv.w,sv.w, s))));
        d = fmaf(hv.x,dv.x, fmaf(hv.y,dv.y, fmaf(hv.z,dv.z, fmaf(hv.w,dv.w, d))));
    }
    as_out[t] = s;
    ad_out[t] = d;
}

// ---------------- per-dst-node softmax aggregation (one warp / node) --------
template<int H, int C>
__global__ void agg_kernel(const float* __restrict__ h,
                           const float* __restrict__ as_in,
                           const float* __restrict__ ad_in,
                           const float* __restrict__ bias,
                           float* __restrict__ out, int N)
{
    constexpr int CH = H*C;
    constexpr int J  = CH/32;
    int warp = (blockIdx.x*blockDim.x + threadIdx.x) >> 5;
    int lane = threadIdx.x & 31;
    if (warp >= N) return;
    const int v = warp;

    float adv = (lane < H) ? ad_in[v*H + lane] : 0.f;
    int b = g_offs[v], e = g_offs[v+1];

    float den = 0.f;
    float acc[J];
    #pragma unroll
    for (int j = 0; j < J; j++) acc[j] = 0.f;

    for (int i = b; i < e; i++) {
        int s = g_srcs[i];
        float ex = 0.f;
        if (lane < H) {
            float ev = as_in[s*H + lane] + adv;
            ev = (ev > 0.f) ? ev : 0.2f*ev;
            ex = __expf(ev);
            den += ex;
        }
        const float* hp = h + (long)s*CH;
        #pragma unroll
        for (int j = 0; j < J; j++) {
            int ch = lane + 32*j;
            float exh = __shfl_sync(0xffffffffu, ex, ch / C);
            acc[j] = fmaf(exh, hp[ch], acc[j]);
        }
    }
    #pragma unroll
    for (int j = 0; j < J; j++) {
        int ch = lane + 32*j;
        float dh = __shfl_sync(0xffffffffu, den, ch / C);
        float o = acc[j]/dh + bias[ch];
        o = (o > 0.f) ? o : expm1f(o);
        out[(long)v*CH + ch] = o;
    }
}

// ---------------- pair head ----------------
__global__ void pair_kernel(const float* __restrict__ x2,
                            const int* __restrict__ n1,
                            const int* __restrict__ n2,
                            const float* __restrict__ linW,
                            const float* __restrict__ linb,
                            float* __restrict__ y, int P)
{
    int p = blockIdx.x*blockDim.x + threadIdx.x;
    if (p >= P) return;
    const float* a  = x2 + (long)n1[p]*CH2;
    const float* bb = x2 + (long)n2[p]*CH2;
    float y0 = linb[0], y1 = linb[1];
    #pragma unroll
    for (int j = 0; j < CH2; j++) {
        float v = a[j];
        y0 = fmaf(v, linW[j*2],   y0);
        y1 = fmaf(v, linW[j*2+1], y1);
    }
    #pragma unroll
    for (int j = 0; j < CH2; j++) {
        float v = bb[j];
        y0 = fmaf(v, linW[(CH2+j)*2],   y0);
        y1 = fmaf(v, linW[(CH2+j)*2+1], y1);
    }
    y[p*2]   = 1.f/(1.f + __expf(-y0));
    y[p*2+1] = 1.f/(1.f + __expf(-y1));
}

// ---------------- launch ----------------
extern "C" void kernel_launch(void* const* d_in, const int* in_sizes, int n_in,
                              void* d_out, int out_size)
{
    const float* features = (const float*)d_in[0];
    const int*   eidx     = (const int*)  d_in[1];
    const int*   n1idx    = (const int*)  d_in[2];
    const int*   n2idx    = (const int*)  d_in[3];
    const float* W1       = (const float*)d_in[4];
    const float* attS1    = (const float*)d_in[5];
    const float* attD1    = (const float*)d_in[6];
    const float* b1       = (const float*)d_in[7];
    const float* W2       = (const float*)d_in[8];
    const float* attS2    = (const float*)d_in[9];
    const float* attD2    = (const float*)d_in[10];
    const float* b2       = (const float*)d_in[11];
    const float* linW     = (const float*)d_in[12];
    const float* linb     = (const float*)d_in[13];

    const int N = N_NODES;
    const int E = in_sizes[1] / 2;
    const int P = in_sizes[2];
    const int etot = E + N;
    const int* srcE = eidx;
    const int* dstE = eidx + E;

    float* y_out  = (float*)d_out;          // [P,2]
    float* x2_out = y_out + (long)P*2;      // [N,64]

    float *p_h1, *p_x1, *p_h2, *p_as1, *p_ad1, *p_as2, *p_ad2;
    cudaGetSymbolAddress((void**)&p_h1,  g_h1);
    cudaGetSymbolAddress((void**)&p_x1,  g_x1);
    cudaGetSymbolAddress((void**)&p_h2,  g_h2);
    cudaGetSymbolAddress((void**)&p_as1, g_as1);
    cudaGetSymbolAddress((void**)&p_ad1, g_ad1);
    cudaGetSymbolAddress((void**)&p_as2, g_as2);
    cudaGetSymbolAddress((void**)&p_ad2, g_ad2);

    // ---- CSR build; gemm1 kept as 4th launch for the ncu sample ----
    zero_kernel<<<(N+255)/256, 256>>>(N);
    count_kernel<<<(etot+255)/256, 256>>>(dstE, E, N);
    int nb = (N + 1023) / 1024;
    scan1_kernel<<<nb, 1024>>>(N);
    {
        dim3 grid((N + 63)/64, CH1/96);
        gemm_tc_kernel<96><<<grid, 256>>>(features, W1, p_h1, N, CH1, NUM_FEA);
    }
    scan2_kernel<<<1, 64>>>(nb);
    scan3_kernel<<<(N+255)/256, 256>>>(N);
    scatter_kernel<<<(etot+255)/256, 256>>>(srcE, dstE, E, N);

    // ---- layer 1 ----
    attn_kernel<HEAD1, HID1><<<(N*HEAD1 + 255)/256, 256>>>(p_h1, attS1, attD1, p_as1, p_ad1, N);
    agg_kernel<HEAD1, HID1><<<(N*32 + 255)/256, 256>>>(p_h1, p_as1, p_ad1, b1, p_x1, N);

    // ---- layer 2 ----
    {
        dim3 grid((N + 63)/64, 1);
        gemm_tc_kernel<64><<<grid, 256>>>(p_x1, W2, p_h2, N, CH2, CH1);
    }
    attn_kernel<HEAD2, HID2><<<(N*HEAD2 + 255)/256, 256>>>(p_h2, attS2, attD2, p_as2, p_ad2, N);
    agg_kernel<HEAD2, HID2><<<(N*32 + 255)/256, 256>>>(p_h2, p_as2, p_ad2, b2, x2_out, N);

    // ---- pair head ----
    pair_kernel<<<(P+255)/256, 256>>>(x2_out, n1idx, n2idx, linW, linb, y_out, P);
}

// round 5
// speedup vs baseline: 1.8814x; 1.5579x over previous
#include <cuda_runtime.h>
#include <math.h>
#include <stdint.h>

// ---------------- problem constants ----------------
#define N_NODES 50000
#define NUM_FEA 213
#define HID1 16
#define HEAD1 12
#define CH1 (HID1*HEAD1)   // 192
#define HID2 8
#define HEAD2 8
#define CH2 (HID2*HEAD2)   // 64
#define E_EDGES 800000
#define E_TOT (E_EDGES + N_NODES)

// ---------------- device scratch ----------------
static __device__ float g_h1[N_NODES*CH1];
static __device__ float g_x1[N_NODES*CH1];
static __device__ float g_h2[N_NODES*CH2];
static __device__ float g_as1[N_NODES*HEAD1];
static __device__ float g_ad1[N_NODES*HEAD1];
static __device__ float g_as2[N_NODES*HEAD2];
static __device__ float g_ad2[N_NODES*HEAD2];
static __device__ int   g_deg[N_NODES];
static __device__ int   g_cur[N_NODES];
static __device__ int   g_tmp[N_NODES];
static __device__ int   g_offs[N_NODES+1];
static __device__ int   g_bsum[64];
static __device__ int   g_srcs[E_TOT];

// ---------------- CSR build ----------------
__global__ void zero_kernel(int n)
{
    int i = blockIdx.x*blockDim.x + threadIdx.x;
    if (i < n) { g_deg[i] = 0; g_cur[i] = 0; }
}

__global__ void count_kernel(const int* __restrict__ dstE, int E, int n)
{
    int i = blockIdx.x*blockDim.x + threadIdx.x;
    int tot = E + n;
    if (i >= tot) return;
    int d = (i < E) ? dstE[i] : (i - E);
    atomicAdd(&g_deg[d], 1);
}

__global__ void scan1_kernel(int n)
{
    __shared__ int sh[1024];
    int t = threadIdx.x;
    int i = blockIdx.x*1024 + t;
    sh[t] = (i < n) ? g_deg[i] : 0;
    __syncthreads();
    #pragma unroll
    for (int off = 1; off < 1024; off <<= 1) {
        int v = 0;
        if (t >= off) v = sh[t-off];
        __syncthreads();
        sh[t] += v;
        __syncthreads();
    }
    if (i < n) g_tmp[i] = sh[t];
    if (t == 1023) g_bsum[blockIdx.x] = sh[1023];
}

__global__ void scan2_kernel(int nb)
{
    __shared__ int sh[64];
    int t = threadIdx.x;
    int mine = (t < nb) ? g_bsum[t] : 0;
    sh[t] = mine;
    __syncthreads();
    #pragma unroll
    for (int off = 1; off < 64; off <<= 1) {
        int v = (t >= off) ? sh[t-off] : 0;
        __syncthreads();
        sh[t] += v;
        __syncthreads();
    }
    if (t < nb) g_bsum[t] = sh[t] - mine;
}

__global__ void scan3_kernel(int n)
{
    int i = blockIdx.x*blockDim.x + threadIdx.x;
    if (i < n) g_offs[i+1] = g_tmp[i] + g_bsum[i >> 10];
    if (i == 0) g_offs[0] = 0;
}

__global__ void scatter_kernel(const int* __restrict__ srcE,
                               const int* __restrict__ dstE, int E, int n)
{
    int i = blockIdx.x*blockDim.x + threadIdx.x;
    int tot = E + n;
    if (i >= tot) return;
    int s, d;
    if (i < E) { s = srcE[i]; d = dstE[i]; }
    else       { s = d = i - E; }
    int pos = g_offs[d] + atomicAdd(&g_cur[d], 1);
    g_srcs[pos] = s;
}

// ---------------- 3xTF32 tensor-core GEMM, pipelined, conflict-free --------
__device__ __forceinline__ uint32_t f2tf32(float x)
{
    uint32_t u;
    asm("cvt.rna.tf32.f32 %0, %1;" : "=r"(u) : "f"(x));
    return u;
}

__device__ __forceinline__ void mma_tf32(float* d, const uint32_t* a, const uint32_t* b)
{
    asm volatile("mma.sync.aligned.m16n8k8.row.col.f32.tf32.tf32.f32 "
                 "{%0,%1,%2,%3}, {%4,%5,%6,%7}, {%8,%9}, {%0,%1,%2,%3};"
                 : "+f"(d[0]), "+f"(d[1]), "+f"(d[2]), "+f"(d[3])
                 : "r"(a[0]), "r"(a[1]), "r"(a[2]), "r"(a[3]),
                   "r"(b[0]), "r"(b[1]));
}

// BM=128, BK=16, 256 threads = 8 warps = 4 m-warps(m32) x 2 n-halves.
// sAhi/sAlo[g(8)][ks(2)][lane(32)][4]  (lane stride 4 u32 -> conflict-free)
// sB[k4(4)][ks(2)][c(BNp)][4] packed {hi_k, hi_k4, lo_k, lo_k4}
template<int BN>
__global__ __launch_bounds__(256, 2)
void gemm_tc_kernel(const float* __restrict__ A,
                    const float* __restrict__ B,
                    float* __restrict__ C,
                    int M, int N, int K)
{
    constexpr int BM = 128, BK = 16;
    constexpr int BNp = BN + 1;
    constexpr int WN = BN/2;
    constexpr int NT = WN/8;                 // 6 (BN=96) or 4 (BN=64)
    constexpr int NSLOT = (8*BN)/256;        // B slots per thread: 3 or 2

    __shared__ uint32_t sAhi[8*2*32*4];      // 8KB
    __shared__ uint32_t sAlo[8*2*32*4];      // 8KB
    __shared__ uint32_t sB[4*2*BNp*4];       // 12.4KB / 8.3KB

    const int tx   = threadIdx.x;
    const int lane = tx & 31;
    const int wid  = tx >> 5;
    const int wm   = wid & 3;                // m-warp: rows wm*32..wm*32+31
    const int wc   = wid >> 2;               // n-half

    const int row0 = blockIdx.x * BM;
    const int col0 = blockIdx.y * BN;

    // staging thread roles
    const int sg  = tx >> 5;                 // A group 0..7
    const int srr = lane >> 2;               // row-in-group (0..7)
    const int scc = lane & 3;                // k-in-half (0..3)

    // clamp addresses so OOB rows never form wild pointers (predicated to 0 anyway)
    const int r0g = row0 + sg*16 + srr;
    const int r1g = r0g + 8;
    const bool r0ok = r0g < M, r1ok = r1g < M;
    const long r0a = (long)(r0ok ? r0g : 0) * K;
    const long r1a = (long)(r1ok ? r1g : 0) * K;

    float av[2][4];                          // A prefetch regs [ks][val]
    float bv[NSLOT][2];                      // B prefetch regs

    float acc[2][NT][4];
    #pragma unroll
    for (int gi = 0; gi < 2; gi++)
        #pragma unroll
        for (int nt = 0; nt < NT; nt++)
            #pragma unroll
            for (int j = 0; j < 4; j++) acc[gi][nt][j] = 0.f;

    const int nk = (K + BK - 1) / BK;

    // ---- prefetch tile 0 ----
    {
        const int k0 = 0;
        #pragma unroll
        for (int ks = 0; ks < 2; ks++) {
            int k = k0 + ks*8 + scc;
            bool kok = k < K, k4ok = (k+4) < K;
            av[ks][0] = (r0ok && kok)  ? A[r0a + k]     : 0.f;
            av[ks][1] = (r1ok && kok)  ? A[r1a + k]     : 0.f;
            av[ks][2] = (r0ok && k4ok) ? A[r0a + k + 4] : 0.f;
            av[ks][3] = (r1ok && k4ok) ? A[r1a + k + 4] : 0.f;
        }
        #pragma unroll
        for (int i = 0; i < NSLOT; i++) {
            int s = tx + i*256;
            int ks = s / (4*BN); int rem = s - ks*4*BN;
            int k4 = rem / BN;   int c   = rem - k4*BN;
            int k = k0 + ks*8 + k4;
            bv[i][0] = (k   < K) ? B[(long)k*N + col0 + c]     : 0.f;
            bv[i][1] = (k+4 < K) ? B[(long)(k+4)*N + col0 + c] : 0.f;
        }
    }

    for (int kt = 0; kt < nk; kt++) {
        // ---- convert + store staged regs to smem ----
        #pragma unroll
        for (int ks = 0; ks < 2; ks++) {
            uint32_t hi[4], lo[4];
            #pragma unroll
            for (int j = 0; j < 4; j++) {
                hi[j] = f2tf32(av[ks][j]);
                lo[j] = f2tf32(av[ks][j] - __uint_as_float(hi[j]));
            }
            int base = ((sg*2 + ks)*32 + lane)*4;
            *(uint4*)&sAhi[base] = make_uint4(hi[0],hi[1],hi[2],hi[3]);
            *(uint4*)&sAlo[base] = make_uint4(lo[0],lo[1],lo[2],lo[3]);
        }
        #pragma unroll
        for (int i = 0; i < NSLOT; i++) {
            int s = tx + i*256;
            int ks = s / (4*BN); int rem = s - ks*4*BN;
            int k4 = rem / BN;   int c   = rem - k4*BN;
            uint32_t h0 = f2tf32(bv[i][0]);
            uint32_t l0 = f2tf32(bv[i][0] - __uint_as_float(h0));
            uint32_t h1 = f2tf32(bv[i][1]);
            uint32_t l1 = f2tf32(bv[i][1] - __uint_as_float(h1));
            *(uint4*)&sB[(((k4*2 + ks)*BNp) + c)*4] = make_uint4(h0, h1, l0, l1);
        }
        __syncthreads();

        // ---- prefetch next tile while computing this one ----
        if (kt + 1 < nk) {
            const int k0 = (kt+1)*BK;
            #pragma unroll
            for (int ks = 0; ks < 2; ks++) {
                int k = k0 + ks*8 + scc;
                bool kok = k < K, k4ok = (k+4) < K;
                av[ks][0] = (r0ok && kok)  ? A[r0a + k]     : 0.f;
                av[ks][1] = (r1ok && kok)  ? A[r1a + k]     : 0.f;
                av[ks][2] = (r0ok && k4ok) ? A[r0a + k + 4] : 0.f;
                av[ks][3] = (r1ok && k4ok) ? A[r1a + k + 4] : 0.f;
            }
            #pragma unroll
            for (int i = 0; i < NSLOT; i++) {
                int s = tx + i*256;
                int ks = s / (4*BN); int rem = s - ks*4*BN;
                int k4 = rem / BN;   int c   = rem - k4*BN;
                int k = k0 + ks*8 + k4;
                bv[i][0] = (k   < K) ? B[(long)k*N + col0 + c]     : 0.f;
                bv[i][1] = (k+4 < K) ? B[(long)(k+4)*N + col0 + c] : 0.f;
            }
        }

        // ---- compute ----
        #pragma unroll
        for (int ks = 0; ks < 2; ks++) {
            uint32_t ahi[2][4], alo[2][4];
            #pragma unroll
            for (int gi = 0; gi < 2; gi++) {
                int g = wm*2 + gi;
                int base = ((g*2 + ks)*32 + lane)*4;
                uint4 h = *(const uint4*)&sAhi[base];
                uint4 l = *(const uint4*)&sAlo[base];
                ahi[gi][0]=h.x; ahi[gi][1]=h.y; ahi[gi][2]=h.z; ahi[gi][3]=h.w;
                alo[gi][0]=l.x; alo[gi][1]=l.y; alo[gi][2]=l.z; alo[gi][3]=l.w;
            }
            #pragma unroll
            for (int nt = 0; nt < NT; nt++) {
                int nc = wc*WN + nt*8 + (lane >> 2);
                uint4 b4 = *(const uint4*)&sB[((((lane&3)*2 + ks)*BNp) + nc)*4];
                uint32_t bhi[2] = {b4.x, b4.y};
                uint32_t blo[2] = {b4.z, b4.w};
                #pragma unroll
                for (int gi = 0; gi < 2; gi++) {
                    mma_tf32(acc[gi][nt], ahi[gi], bhi);
                    mma_tf32(acc[gi][nt], ahi[gi], blo);
                    mma_tf32(acc[gi][nt], alo[gi], bhi);
                }
            }
        }
        __syncthreads();
    }

    // ---- epilogue ----
    #pragma unroll
    for (int gi = 0; gi < 2; gi++) {
        int gr0 = row0 + (wm*2 + gi)*16 + (lane >> 2);
        int gr1 = gr0 + 8;
        #pragma unroll
        for (int nt = 0; nt < NT; nt++) {
            int gc = col0 + wc*WN + nt*8 + (lane & 3)*2;
            if (gr0 < M)
                *(float2*)&C[(long)gr0*N + gc] = make_float2(acc[gi][nt][0], acc[gi][nt][1]);
            if (gr1 < M)
                *(float2*)&C[(long)gr1*N + gc] = make_float2(acc[gi][nt][2], acc[gi][nt][3]);
        }
    }
}

// ---------------- attention scores ----------------
template<int H, int C>
__global__ void attn_kernel(const float* __restrict__ h,
                            const float* __restrict__ att_s,
                            const float* __restrict__ att_d,
                            float* __restrict__ as_out,
                            float* __restrict__ ad_out, int N)
{
    int t = blockIdx.x*blockDim.x + threadIdx.x;
    if (t >= N*H) return;
    int hh = t % H;
    const float* hp = h + (long)t * C;
    const float* sp = att_s + hh*C;
    const float* dp = att_d + hh*C;
    float s = 0.f, d = 0.f;
    #pragma unroll
    for (int c = 0; c < C; c += 4) {
        float4 hv = *(const float4*)&hp[c];
        float4 sv = *(const float4*)&sp[c];
        float4 dv = *(const float4*)&dp[c];
        s = fmaf(hv.x,sv.x, fmaf(hv.y,sv.y, fmaf(hv.z,sv.z, fmaf(hv.w,sv.w, s))));
        d = fmaf(hv.x,dv.x, fmaf(hv.y,dv.y, fmaf(hv.z,dv.z, fmaf(hv.w,dv.w, d))));
    }
    as_out[t] = s;
    ad_out[t] = d;
}

// ---------------- per-dst-node softmax aggregation (one warp / node) --------
template<int H, int C>
__global__ void agg_kernel(const float* __restrict__ h,
                           const float* __restrict__ as_in,
                           const float* __restrict__ ad_in,
                           const float* __restrict__ bias,
                           float* __restrict__ out, int N)
{
    constexpr int CH = H*C;
    constexpr int J  = CH/32;
    int warp = (blockIdx.x*blockDim.x + threadIdx.x) >> 5;
    int lane = threadIdx.x & 31;
    if (warp >= N) return;
    const int v = warp;

    float adv = (lane < H) ? ad_in[v*H + lane] : 0.f;
    int b = g_offs[v], e = g_offs[v+1];

    float den = 0.f;
    float acc[J];
    #pragma unroll
    for (int j = 0; j < J; j++) acc[j] = 0.f;

    for (int i = b; i < e; i++) {
        int s = g_srcs[i];
        float ex = 0.f;
        if (lane < H) {
            float ev = as_in[s*H + lane] + adv;
            ev = (ev > 0.f) ? ev : 0.2f*ev;
            ex = __expf(ev);
            den += ex;
        }
        const float* hp = h + (long)s*CH;
        #pragma unroll
        for (int j = 0; j < J; j++) {
            int ch = lane + 32*j;
            float exh = __shfl_sync(0xffffffffu, ex, ch / C);
            acc[j] = fmaf(exh, hp[ch], acc[j]);
        }
    }
    #pragma unroll
    for (int j = 0; j < J; j++) {
        int ch = lane + 32*j;
        float dh = __shfl_sync(0xffffffffu, den, ch / C);
        float o = acc[j]/dh + bias[ch];
        o = (o > 0.f) ? o : expm1f(o);
        out[(long)v*CH + ch] = o;
    }
}

// ---------------- pair head ----------------
__global__ void pair_kernel(const float* __restrict__ x2,
                            const int* __restrict__ n1,
                            const int* __restrict__ n2,
                            const float* __restrict__ linW,
                            const float* __restrict__ linb,
                            float* __restrict__ y, int P)
{
    int p = blockIdx.x*blockDim.x + threadIdx.x;
    if (p >= P) return;
    const float* a  = x2 + (long)n1[p]*CH2;
    const float* bb = x2 + (long)n2[p]*CH2;
    float y0 = linb[0], y1 = linb[1];
    #pragma unroll
    for (int j = 0; j < CH2; j++) {
        float v = a[j];
        y0 = fmaf(v, linW[j*2],   y0);
        y1 = fmaf(v, linW[j*2+1], y1);
    }
    #pragma unroll
    for (int j = 0; j < CH2; j++) {
        float v = bb[j];
        y0 = fmaf(v, linW[(CH2+j)*2],   y0);
        y1 = fmaf(v, linW[(CH2+j)*2+1], y1);
    }
    y[p*2]   = 1.f/(1.f + __expf(-y0));
    y[p*2+1] = 1.f/(1.f + __expf(-y1));
}

// ---------------- launch ----------------
extern "C" void kernel_launch(void* const* d_in, const int* in_sizes, int n_in,
                              void* d_out, int out_size)
{
    const float* features = (const float*)d_in[0];
    const int*   eidx     = (const int*)  d_in[1];
    const int*   n1idx    = (const int*)  d_in[2];
    const int*   n2idx    = (const int*)  d_in[3];
    const float* W1       = (const float*)d_in[4];
    const float* attS1    = (const float*)d_in[5];
    const float* attD1    = (const float*)d_in[6];
    const float* b1       = (const float*)d_in[7];
    const float* W2       = (const float*)d_in[8];
    const float* attS2    = (const float*)d_in[9];
    const float* attD2    = (const float*)d_in[10];
    const float* b2       = (const float*)d_in[11];
    const float* linW     = (const float*)d_in[12];
    const float* linb     = (const float*)d_in[13];

    const int N = N_NODES;
    const int E = in_sizes[1] / 2;
    const int P = in_sizes[2];
    const int etot = E + N;
    const int* srcE = eidx;
    const int* dstE = eidx + E;

    float* y_out  = (float*)d_out;          // [P,2]
    float* x2_out = y_out + (long)P*2;      // [N,64]

    float *p_h1, *p_x1, *p_h2, *p_as1, *p_ad1, *p_as2, *p_ad2;
    cudaGetSymbolAddress((void**)&p_h1,  g_h1);
    cudaGetSymbolAddress((void**)&p_x1,  g_x1);
    cudaGetSymbolAddress((void**)&p_h2,  g_h2);
    cudaGetSymbolAddress((void**)&p_as1, g_as1);
    cudaGetSymbolAddress((void**)&p_ad1, g_ad1);
    cudaGetSymbolAddress((void**)&p_as2, g_as2);
    cudaGetSymbolAddress((void**)&p_ad2, g_ad2);

    // ---- CSR build; gemm1 kept as 4th launch for the ncu sample ----
    zero_kernel<<<(N+255)/256, 256>>>(N);
    count_kernel<<<(etot+255)/256, 256>>>(dstE, E, N);
    int nb = (N + 1023) / 1024;
    scan1_kernel<<<nb, 1024>>>(N);
    {
        dim3 grid((N + 127)/128, CH1/96);
        gemm_tc_kernel<96><<<grid, 256>>>(features, W1, p_h1, N, CH1, NUM_FEA);
    }
    scan2_kernel<<<1, 64>>>(nb);
    scan3_kernel<<<(N+255)/256, 256>>>(N);
    scatter_kernel<<<(etot+255)/256, 256>>>(srcE, dstE, E, N);

    // ---- layer 1 ----
    attn_kernel<HEAD1, HID1><<<(N*HEAD1 + 255)/256, 256>>>(p_h1, attS1, attD1, p_as1, p_ad1, N);
    agg_kernel<HEAD1, HID1><<<(N*32 + 255)/256, 256>>>(p_h1, p_as1, p_ad1, b1, p_x1, N);

    // ---- layer 2 ----
    {
        dim3 grid((N + 127)/128, 1);
        gemm_tc_kernel<64><<<grid, 256>>>(p_x1, W2, p_h2, N, CH2, CH1);
    }
    attn_kernel<HEAD2, HID2><<<(N*HEAD2 + 255)/256, 256>>>(p_h2, attS2, attD2, p_as2, p_ad2, N);
    agg_kernel<HEAD2, HID2><<<(N*32 + 255)/256, 256>>>(p_h2, p_as2, p_ad2, b2, x2_out, N);

    // ---- pair head ----
    pair_kernel<<<(P+255)/256, 256>>>(x2_out, n1idx, n2idx, linW, linb, y_out, P);
}

// round 7
// speedup vs baseline: 1.9208x; 1.0209x over previous
#include <cuda_runtime.h>
#include <math.h>
#include <stdint.h>

// ---------------- problem constants ----------------
#define N_NODES 50000
#define NUM_FEA 213
#define HID1 16
#define HEAD1 12
#define CH1 (HID1*HEAD1)   // 192
#define HID2 8
#define HEAD2 8
#define CH2 (HID2*HEAD2)   // 64
#define E_EDGES 800000
#define E_TOT (E_EDGES + N_NODES)

// ---------------- device scratch ----------------
static __device__ float g_h1[N_NODES*CH1];
static __device__ float g_x1[N_NODES*CH1];
static __device__ float g_h2[N_NODES*CH2];
static __device__ float g_as1[N_NODES*HEAD1];
static __device__ float g_ad1[N_NODES*HEAD1];
static __device__ float g_as2[N_NODES*HEAD2];
static __device__ float g_ad2[N_NODES*HEAD2];
static __device__ int   g_deg[N_NODES];
static __device__ int   g_cur[N_NODES];
static __device__ int   g_tmp[N_NODES];
static __device__ int   g_offs[N_NODES+1];
static __device__ int   g_bsum[64];
static __device__ int   g_srcs[E_TOT];

// ---------------- CSR build ----------------
__global__ void zero_kernel(int n)
{
    int i = blockIdx.x*blockDim.x + threadIdx.x;
    if (i < n) { g_deg[i] = 0; g_cur[i] = 0; }
}

__global__ void count_kernel(const int* __restrict__ dstE, int E, int n)
{
    int i = blockIdx.x*blockDim.x + threadIdx.x;
    int tot = E + n;
    if (i >= tot) return;
    int d = (i < E) ? dstE[i] : (i - E);
    atomicAdd(&g_deg[d], 1);
}

__global__ void scan1_kernel(int n)
{
    __shared__ int sh[1024];
    int t = threadIdx.x;
    int i = blockIdx.x*1024 + t;
    sh[t] = (i < n) ? g_deg[i] : 0;
    __syncthreads();
    #pragma unroll
    for (int off = 1; off < 1024; off <<= 1) {
        int v = 0;
        if (t >= off) v = sh[t-off];
        __syncthreads();
        sh[t] += v;
        __syncthreads();
    }
    if (i < n) g_tmp[i] = sh[t];
    if (t == 1023) g_bsum[blockIdx.x] = sh[1023];
}

__global__ void scan2_kernel(int nb)
{
    __shared__ int sh[64];
    int t = threadIdx.x;
    int mine = (t < nb) ? g_bsum[t] : 0;
    sh[t] = mine;
    __syncthreads();
    #pragma unroll
    for (int off = 1; off < 64; off <<= 1) {
        int v = (t >= off) ? sh[t-off] : 0;
        __syncthreads();
        sh[t] += v;
        __syncthreads();
    }
    if (t < nb) g_bsum[t] = sh[t] - mine;
}

__global__ void scan3_kernel(int n)
{
    int i = blockIdx.x*blockDim.x + threadIdx.x;
    if (i < n) g_offs[i+1] = g_tmp[i] + g_bsum[i >> 10];
    if (i == 0) g_offs[0] = 0;
}

__global__ void scatter_kernel(const int* __restrict__ srcE,
                               const int* __restrict__ dstE, int E, int n)
{
    int i = blockIdx.x*blockDim.x + threadIdx.x;
    int tot = E + n;
    if (i >= tot) return;
    int s, d;
    if (i < E) { s = srcE[i]; d = dstE[i]; }
    else       { s = d = i - E; }
    int pos = g_offs[d] + atomicAdd(&g_cur[d], 1);
    g_srcs[pos] = s;
}

// ---------------- 3xTF32 tensor-core GEMM, double-buffered pipeline --------
__device__ __forceinline__ uint32_t f2tf32(float x)
{
    uint32_t u;
    asm("cvt.rna.tf32.f32 %0, %1;" : "=r"(u) : "f"(x));
    return u;
}

__device__ __forceinline__ void mma_tf32(float* d, const uint32_t* a, const uint32_t* b)
{
    asm volatile("mma.sync.aligned.m16n8k8.row.col.f32.tf32.tf32.f32 "
                 "{%0,%1,%2,%3}, {%4,%5,%6,%7}, {%8,%9}, {%0,%1,%2,%3};"
                 : "+f"(d[0]), "+f"(d[1]), "+f"(d[2]), "+f"(d[3])
                 : "r"(a[0]), "r"(a[1]), "r"(a[2]), "r"(a[3]),
                   "r"(b[0]), "r"(b[1]));
}

// BM=128, BK=16, 256 threads = 8 warps = 4 m-warps(m32) x 2 n-halves.
// Stage s: sAhi/sAlo[s][g(8)][ks(2)][lane(32)][4], sB[s][k4(4)][ks(2)][c(BNp)][4]
template<int BN>
__global__ __launch_bounds__(256, 2)
void gemm_tc_kernel(const float* __restrict__ A,
                    const float* __restrict__ B,
                    float* __restrict__ C,
                    int M, int N, int K)
{
    constexpr int BM = 128, BK = 16;
    constexpr int BNp = BN + 1;
    constexpr int WN = BN/2;
    constexpr int NT = WN/8;                 // 6 (BN=96) or 4 (BN=64)
    constexpr int NSLOT = (8*BN)/256;        // 3 or 2
    constexpr int ASZ = 8*2*32*4;            // 2048 u32
    constexpr int BSZ = 4*2*BNp*4;

    __shared__ uint32_t sAhi[2][ASZ];
    __shared__ uint32_t sAlo[2][ASZ];
    __shared__ uint32_t sB[2][BSZ];

    const int tx   = threadIdx.x;
    const int lane = tx & 31;
    const int wid  = tx >> 5;
    const int wm   = wid & 3;
    const int wc   = wid >> 2;

    const int row0 = blockIdx.x * BM;
    const int col0 = blockIdx.y * BN;

    const int sg  = tx >> 5;
    const int srr = lane >> 2;
    const int scc = lane & 3;

    const int r0g = row0 + sg*16 + srr;
    const int r1g = r0g + 8;
    const bool r0ok = r0g < M, r1ok = r1g < M;
    const long r0a = (long)(r0ok ? r0g : 0) * K;
    const long r1a = (long)(r1ok ? r1g : 0) * K;

    float av[2][4];
    float bv[NSLOT][2];

    float acc[2][NT][4];
    #pragma unroll
    for (int gi = 0; gi < 2; gi++)
        #pragma unroll
        for (int nt = 0; nt < NT; nt++)
            #pragma unroll
            for (int j = 0; j < 4; j++) acc[gi][nt][j] = 0.f;

    const int nk = (K + BK - 1) / BK;

    auto load_regs = [&](int kt) {
        const int k0 = kt * BK;
        #pragma unroll
        for (int ks = 0; ks < 2; ks++) {
            int k = k0 + ks*8 + scc;
            bool kok = k < K, k4ok = (k+4) < K;
            av[ks][0] = (r0ok && kok)  ? A[r0a + k]     : 0.f;
            av[ks][1] = (r1ok && kok)  ? A[r1a + k]     : 0.f;
            av[ks][2] = (r0ok && k4ok) ? A[r0a + k + 4] : 0.f;
            av[ks][3] = (r1ok && k4ok) ? A[r1a + k + 4] : 0.f;
        }
        #pragma unroll
        for (int i = 0; i < NSLOT; i++) {
            int s = tx + i*256;
            int ks = s / (4*BN); int rem = s - ks*4*BN;
            int k4 = rem / BN;   int c   = rem - k4*BN;
            int k = k0 + ks*8 + k4;
            bv[i][0] = (k   < K) ? B[(long)k*N + col0 + c]     : 0.f;
            bv[i][1] = (k+4 < K) ? B[(long)(k+4)*N + col0 + c] : 0.f;
        }
    };

    auto cvt_sts = [&](int buf) {
        #pragma unroll
        for (int ks = 0; ks < 2; ks++) {
            uint32_t hi[4], lo[4];
            #pragma unroll
            for (int j = 0; j < 4; j++) {
                hi[j] = f2tf32(av[ks][j]);
                lo[j] = f2tf32(av[ks][j] - __uint_as_float(hi[j]));
            }
            int base = ((sg*2 + ks)*32 + lane)*4;
            *(uint4*)&sAhi[buf][base] = make_uint4(hi[0],hi[1],hi[2],hi[3]);
            *(uint4*)&sAlo[buf][base] = make_uint4(lo[0],lo[1],lo[2],lo[3]);
        }
        #pragma unroll
        for (int i = 0; i < NSLOT; i++) {
            int s = tx + i*256;
            int ks = s / (4*BN); int rem = s - ks*4*BN;
            int k4 = rem / BN;   int c   = rem - k4*BN;
            uint32_t h0 = f2tf32(bv[i][0]);
            uint32_t l0 = f2tf32(bv[i][0] - __uint_as_float(h0));
            uint32_t h1 = f2tf32(bv[i][1]);
            uint32_t l1 = f2tf32(bv[i][1] - __uint_as_float(h1));
            *(uint4*)&sB[buf][(((k4*2 + ks)*BNp) + c)*4] = make_uint4(h0, h1, l0, l1);
        }
    };

    auto compute = [&](int buf) {
        #pragma unroll
        for (int ks = 0; ks < 2; ks++) {
            uint32_t ahi[2][4], alo[2][4];
            #pragma unroll
            for (int gi = 0; gi < 2; gi++) {
                int g = wm*2 + gi;
                int base = ((g*2 + ks)*32 + lane)*4;
                uint4 h = *(const uint4*)&sAhi[buf][base];
                uint4 l = *(const uint4*)&sAlo[buf][base];
                ahi[gi][0]=h.x; ahi[gi][1]=h.y; ahi[gi][2]=h.z; ahi[gi][3]=h.w;
                alo[gi][0]=l.x; alo[gi][1]=l.y; alo[gi][2]=l.z; alo[gi][3]=l.w;
            }
            #pragma unroll
            for (int nt = 0; nt < NT; nt++) {
                int nc = wc*WN + nt*8 + (lane >> 2);
                uint4 b4 = *(const uint4*)&sB[buf][((((lane&3)*2 + ks)*BNp) + nc)*4];
                uint32_t bhi[2] = {b4.x, b4.y};
                uint32_t blo[2] = {b4.z, b4.w};
                #pragma unroll
                for (int gi = 0; gi < 2; gi++) {
                    mma_tf32(acc[gi][nt], ahi[gi], bhi);
                    mma_tf32(acc[gi][nt], ahi[gi], blo);
                    mma_tf32(acc[gi][nt], alo[gi], bhi);
                }
            }
        }
    };

    // ---- prologue: stage tile 0, issue LDG for tile 1 ----
    load_regs(0);
    cvt_sts(0);
    if (nk > 1) load_regs(1);
    __syncthreads();

    for (int kt = 0; kt < nk; kt++) {
        compute(kt & 1);
        if (kt + 1 < nk) {
            cvt_sts((kt + 1) & 1);
            __syncthreads();
            if (kt + 2 < nk) load_regs(kt + 2);
        }
    }

    // ---- epilogue ----
    #pragma unroll
    for (int gi = 0; gi < 2; gi++) {
        int gr0 = row0 + (wm*2 + gi)*16 + (lane >> 2);
        int gr1 = gr0 + 8;
        #pragma unroll
        for (int nt = 0; nt < NT; nt++) {
            int gc = col0 + wc*WN + nt*8 + (lane & 3)*2;
            if (gr0 < M)
                *(float2*)&C[(long)gr0*N + gc] = make_float2(acc[gi][nt][0], acc[gi][nt][1]);
            if (gr1 < M)
                *(float2*)&C[(long)gr1*N + gc] = make_float2(acc[gi][nt][2], acc[gi][nt][3]);
        }
    }
}

// ---------------- attention scores ----------------
template<int H, int C>
__global__ void attn_kernel(const float* __restrict__ h,
                            const float* __restrict__ att_s,
                            const float* __restrict__ att_d,
                            float* __restrict__ as_out,
                            float* __restrict__ ad_out, int N)
{
    int t = blockIdx.x*blockDim.x + threadIdx.x;
    if (t >= N*H) return;
    int hh = t % H;
    const float* hp = h + (long)t * C;
    const float* sp = att_s + hh*C;
    const float* dp = att_d + hh*C;
    float s = 0.f, d = 0.f;
    #pragma unroll
    for (int c = 0; c < C; c += 4) {
        float4 hv = *(const float4*)&hp[c];
        float4 sv = *(const float4*)&sp[c];
        float4 dv = *(const float4*)&dp[c];
        s = fmaf(hv.x,sv.x, fmaf(hv.y,sv.y, fmaf(hv.z,sv.z, fmaf(hv.w,sv.w, s))));
        d = fmaf(hv.x,dv.x, fmaf(hv.y,dv.y, fmaf(hv.z,dv.z, fmaf(hv.w,dv.w, d))));
    }
    as_out[t] = s;
    ad_out[t] = d;
}

// ---------------- per-dst-node softmax aggregation (one warp / node) --------
template<int H, int C>
__global__ void agg_kernel(const float* __restrict__ h,
                           const float* __restrict__ as_in,
                           const float* __restrict__ ad_in,
                           const float* __restrict__ bias,
                           float* __restrict__ out, int N)
{
    constexpr int CH = H*C;
    constexpr int J  = CH/32;
    int warp = (blockIdx.x*blockDim.x + threadIdx.x) >> 5;
    int lane = threadIdx.x & 31;
    if (warp >= N) return;
    const int v = warp;

    float adv = (lane < H) ? ad_in[v*H + lane] : 0.f;
    int b = g_offs[v], e = g_offs[v+1];

    float den = 0.f;
    float acc[J];
    #pragma unroll
    for (int j = 0; j < J; j++) acc[j] = 0.f;

    if (b < e) {
        int s = g_srcs[b];                           // head of pointer chase
        for (int i = b; i < e; i++) {
            int s_next = (i+1 < e) ? g_srcs[i+1] : s; // prefetch next src idx
            float ex = 0.f;
            if (lane < H) {
                float ev = as_in[s*H + lane] + adv;
                ev = (ev > 0.f) ? ev : 0.2f*ev;
                ex = __expf(ev);
                den += ex;
            }
            const float* hp = h + (long)s*CH;
            #pragma unroll
            for (int j = 0; j < J; j++) {
                int ch = lane + 32*j;
                float exh = __shfl_sync(0xffffffffu, ex, ch / C);
                acc[j] = fmaf(exh, hp[ch], acc[j]);
            }
            s = s_next;
        }
    }
    #pragma unroll
    for (int j = 0; j < J; j++) {
        int ch = lane + 32*j;
        float dh = __shfl_sync(0xffffffffu, den, ch / C);
        float o = acc[j]/dh + bias[ch];
        o = (o > 0.f) ? o : expm1f(o);
        out[(long)v*CH + ch] = o;
    }
}

// ---------------- pair head ----------------
__global__ void pair_kernel(const float* __restrict__ x2,
                            const int* __restrict__ n1,
                            const int* __restrict__ n2,
                            const float* __restrict__ linW,
                            const float* __restrict__ linb,
                            float* __restrict__ y, int P)
{
    int p = blockIdx.x*blockDim.x + threadIdx.x;
    if (p >= P) return;
    const float* a  = x2 + (long)n1[p]*CH2;
    const float* bb = x2 + (long)n2[p]*CH2;
    float y0 = linb[0], y1 = linb[1];
    #pragma unroll
    for (int j = 0; j < CH2; j++) {
        float v = a[j];
        y0 = fmaf(v, linW[j*2],   y0);
        y1 = fmaf(v, linW[j*2+1], y1);
    }
    #pragma unroll
    for (int j = 0; j < CH2; j++) {
        float v = bb[j];
        y0 = fmaf(v, linW[(CH2+j)*2],   y0);
        y1 = fmaf(v, linW[(CH2+j)*2+1], y1);
    }
    y[p*2]   = 1.f/(1.f + __expf(-y0));
    y[p*2+1] = 1.f/(1.f + __expf(-y1));
}

// ---------------- launch ----------------
extern "C" void kernel_launch(void* const* d_in, const int* in_sizes, int n_in,
                              void* d_out, int out_size)
{
    const float* features = (const float*)d_in[0];
    const int*   eidx     = (const int*)  d_in[1];
    const int*   n1idx    = (const int*)  d_in[2];
    const int*   n2idx    = (const int*)  d_in[3];
    const float* W1       = (const float*)d_in[4];
    const float* attS1    = (const float*)d_in[5];
    const float* attD1    = (const float*)d_in[6];
    const float* b1       = (const float*)d_in[7];
    const float* W2       = (const float*)d_in[8];
    const float* attS2    = (const float*)d_in[9];
    const float* attD2    = (const float*)d_in[10];
    const float* b2       = (const float*)d_in[11];
    const float* linW     = (const float*)d_in[12];
    const float* linb     = (const float*)d_in[13];

    const int N = N_NODES;
    const int E = in_sizes[1] / 2;
    const int P = in_sizes[2];
    const int etot = E + N;
    const int* srcE = eidx;
    const int* dstE = eidx + E;

    float* y_out  = (float*)d_out;          // [P,2]
    float* x2_out = y_out + (long)P*2;      // [N,64]

    float *p_h1, *p_x1, *p_h2, *p_as1, *p_ad1, *p_as2, *p_ad2;
    cudaGetSymbolAddress((void**)&p_h1,  g_h1);
    cudaGetSymbolAddress((void**)&p_x1,  g_x1);
    cudaGetSymbolAddress((void**)&p_h2,  g_h2);
    cudaGetSymbolAddress((void**)&p_as1, g_as1);
    cudaGetSymbolAddress((void**)&p_ad1, g_ad1);
    cudaGetSymbolAddress((void**)&p_as2, g_as2);
    cudaGetSymbolAddress((void**)&p_ad2, g_ad2);

    // ---- CSR build; gemm1 kept as 4th launch for the ncu sample ----
    zero_kernel<<<(N+255)/256, 256>>>(N);
    count_kernel<<<(etot+255)/256, 256>>>(dstE, E, N);
    int nb = (N + 1023) / 1024;
    scan1_kernel<<<nb, 1024>>>(N);
    {
        dim3 grid((N + 127)/128, CH1/96);
        gemm_tc_kernel<96><<<grid, 256>>>(features, W1, p_h1, N, CH1, NUM_FEA);
    }
    scan2_kernel<<<1, 64>>>(nb);
    scan3_kernel<<<(N+255)/256, 256>>>(N);
    scatter_kernel<<<(etot+255)/256, 256>>>(srcE, dstE, E, N);

    // ---- layer 1 ----
    attn_kernel<HEAD1, HID1><<<(N*HEAD1 + 255)/256, 256>>>(p_h1, attS1, attD1, p_as1, p_ad1, N);
    agg_kernel<HEAD1, HID1><<<(N*32 + 255)/256, 256>>>(p_h1, p_as1, p_ad1, b1, p_x1, N);

    // ---- layer 2 ----
    {
        dim3 grid((N + 127)/128, 1);
        gemm_tc_kernel<64><<<grid, 256>>>(p_x1, W2, p_h2, N, CH2, CH1);
    }
    attn_kernel<HEAD2, HID2><<<(N*HEAD2 + 255)/256, 256>>>(p_h2, attS2, attD2, p_as2, p_ad2, N);
    agg_kernel<HEAD2, HID2><<<(N*32 + 255)/256, 256>>>(p_h2, p_as2, p_ad2, b2, x2_out, N);

    // ---- pair head ----
    pair_kernel<<<(P+255)/256, 256>>>(x2_out, n1idx, n2idx, linW, linb, y_out, P);
}

// round 8
// speedup vs baseline: 2.1705x; 1.1300x over previous
#include <cuda_runtime.h>
#include <math.h>
#include <stdint.h>

// ---------------- problem constants ----------------
#define N_NODES 50000
#define NUM_FEA 213
#define HID1 16
#define HEAD1 12
#define CH1 (HID1*HEAD1)   // 192
#define HID2 8
#define HEAD2 8
#define CH2 (HID2*HEAD2)   // 64
#define E_EDGES 800000
#define E_TOT (E_EDGES + N_NODES)

// ---------------- device scratch ----------------
static __device__ float g_h1[N_NODES*CH1];
static __device__ float g_x1[N_NODES*CH1];
static __device__ float g_h2[N_NODES*CH2];
static __device__ float g_as1[N_NODES*HEAD1];
static __device__ float g_ad1[N_NODES*HEAD1];
static __device__ float g_as2[N_NODES*HEAD2];
static __device__ float g_ad2[N_NODES*HEAD2];
static __device__ int   g_deg[N_NODES];
static __device__ int   g_cur[N_NODES];
static __device__ int   g_tmp[N_NODES];
static __device__ int   g_offs[N_NODES+1];
static __device__ int   g_bsum[64];
static __device__ int   g_srcs[E_TOT];

// ---------------- CSR build ----------------
__global__ void zero_kernel(int n)
{
    int i = blockIdx.x*blockDim.x + threadIdx.x;
    if (i < n) { g_deg[i] = 0; g_cur[i] = 0; }
}

__global__ void count_kernel(const int* __restrict__ dstE, int E, int n)
{
    int i = blockIdx.x*blockDim.x + threadIdx.x;
    int tot = E + n;
    if (i >= tot) return;
    int d = (i < E) ? dstE[i] : (i - E);
    atomicAdd(&g_deg[d], 1);
}

__global__ void scan1_kernel(int n)
{
    __shared__ int sh[1024];
    int t = threadIdx.x;
    int i = blockIdx.x*1024 + t;
    sh[t] = (i < n) ? g_deg[i] : 0;
    __syncthreads();
    #pragma unroll
    for (int off = 1; off < 1024; off <<= 1) {
        int v = 0;
        if (t >= off) v = sh[t-off];
        __syncthreads();
        sh[t] += v;
        __syncthreads();
    }
    if (i < n) g_tmp[i] = sh[t];
    if (t == 1023) g_bsum[blockIdx.x] = sh[1023];
}

__global__ void scan2_kernel(int nb)
{
    __shared__ int sh[64];
    int t = threadIdx.x;
    int mine = (t < nb) ? g_bsum[t] : 0;
    sh[t] = mine;
    __syncthreads();
    #pragma unroll
    for (int off = 1; off < 64; off <<= 1) {
        int v = (t >= off) ? sh[t-off] : 0;
        __syncthreads();
        sh[t] += v;
        __syncthreads();
    }
    if (t < nb) g_bsum[t] = sh[t] - mine;
}

__global__ void scan3_kernel(int n)
{
    int i = blockIdx.x*blockDim.x + threadIdx.x;
    if (i < n) g_offs[i+1] = g_tmp[i] + g_bsum[i >> 10];
    if (i == 0) g_offs[0] = 0;
}

__global__ void scatter_kernel(const int* __restrict__ srcE,
                               const int* __restrict__ dstE, int E, int n)
{
    int i = blockIdx.x*blockDim.x + threadIdx.x;
    int tot = E + n;
    if (i >= tot) return;
    int s, d;
    if (i < E) { s = srcE[i]; d = dstE[i]; }
    else       { s = d = i - E; }
    int pos = g_offs[d] + atomicAdd(&g_cur[d], 1);
    g_srcs[pos] = s;
}

// ---------------- 3x-bf16 tensor-core GEMM (m16n8k16), double-buffered -----
__device__ __forceinline__ uint32_t pack2(float v0, float v1)   // lo16=bf(v0), hi16=bf(v1)
{
    uint32_t d;
    asm("cvt.rn.bf16x2.f32 %0, %1, %2;" : "=r"(d) : "f"(v1), "f"(v0));
    return d;
}
__device__ __forceinline__ float lo_f(uint32_t d) { return __uint_as_float(d << 16); }
__device__ __forceinline__ float hi_f(uint32_t d) { return __uint_as_float(d & 0xffff0000u); }

__device__ __forceinline__ void mma_bf16(float* d, const uint32_t* a, const uint32_t* b)
{
    asm volatile("mma.sync.aligned.m16n8k16.row.col.f32.bf16.bf16.f32 "
                 "{%0,%1,%2,%3}, {%4,%5,%6,%7}, {%8,%9}, {%0,%1,%2,%3};"
                 : "+f"(d[0]), "+f"(d[1]), "+f"(d[2]), "+f"(d[3])
                 : "r"(a[0]), "r"(a[1]), "r"(a[2]), "r"(a[3]),
                   "r"(b[0]), "r"(b[1]));
}

// BM=128, BK=16, 256 threads = 8 warps = 4 m-warps(m32, gi 0..1) x 2 n-halves.
// sA[s][g(8)][hl(2)][lane(32)][4]  (lane stride 4 -> conflict-free)
// sB[s][tg(4)][c(BNp)][4] = {bhi0,bhi1,blo0,blo1}; BNp=BN+2 -> conflict-free
template<int BN>
__global__ __launch_bounds__(256, 2)
void gemm_tc_kernel(const float* __restrict__ A,
                    const float* __restrict__ B,
                    float* __restrict__ C,
                    int M, int N, int K)
{
    constexpr int BM = 128, BK = 16;
    constexpr int BNp = BN + 2;
    constexpr int WN = BN/2;
    constexpr int NT = WN/8;                 // 6 (BN=96) or 4 (BN=64)
    constexpr int NBS = (4*BN + 255)/256;    // B staging iters (2 or 1)
    constexpr int ASZ = 8*2*32*4;            // 2048 u32
    constexpr int BSZ = 4*BNp*4;

    __shared__ uint32_t sA[2][ASZ];
    __shared__ uint32_t sB[2][BSZ];

    const int tx   = threadIdx.x;
    const int lane = tx & 31;
    const int wid  = tx >> 5;
    const int wm   = wid & 3;
    const int wc   = wid >> 2;

    const int row0 = blockIdx.x * BM;
    const int col0 = blockIdx.y * BN;

    const int sg  = tx >> 5;                 // A staging group
    const int srr = lane >> 2;
    const int scc = lane & 3;

    const int r0g = row0 + sg*16 + srr;
    const int r1g = r0g + 8;
    const bool r0ok = r0g < M, r1ok = r1g < M;
    const long r0a = (long)(r0ok ? r0g : 0) * K;
    const long r1a = (long)(r1ok ? r1g : 0) * K;

    float av[2][4];                          // [p: k-pair half][r0k, r0k1, r1k, r1k1]
    float bv[NBS][4];

    float acc[2][NT][4];
    #pragma unroll
    for (int gi = 0; gi < 2; gi++)
        #pragma unroll
        for (int nt = 0; nt < NT; nt++)
            #pragma unroll
            for (int j = 0; j < 4; j++) acc[gi][nt][j] = 0.f;

    const int nk = (K + BK - 1) / BK;

    auto load_regs = [&](int kt) {
        const int k0 = kt * BK;
        #pragma unroll
        for (int p = 0; p < 2; p++) {
            int kq = k0 + 2*scc + 8*p;
            bool k0ok = kq < K, k1ok = (kq+1) < K;
            av[p][0] = (r0ok && k0ok) ? A[r0a + kq]     : 0.f;
            av[p][1] = (r0ok && k1ok) ? A[r0a + kq + 1] : 0.f;
            av[p][2] = (r1ok && k0ok) ? A[r1a + kq]     : 0.f;
            av[p][3] = (r1ok && k1ok) ? A[r1a + kq + 1] : 0.f;
        }
        #pragma unroll
        for (int i = 0; i < NBS; i++) {
            int s = tx + i*256;
            if (s < 4*BN) {
                int tg = s / BN, c = s - tg*BN;
                int k = k0 + 2*tg;
                bv[i][0] = (k   < K) ? B[(long)k*N     + col0 + c] : 0.f;
                bv[i][1] = (k+1 < K) ? B[(long)(k+1)*N + col0 + c] : 0.f;
                bv[i][2] = (k+8 < K) ? B[(long)(k+8)*N + col0 + c] : 0.f;
                bv[i][3] = (k+9 < K) ? B[(long)(k+9)*N + col0 + c] : 0.f;
            }
        }
    };

    auto cvt_sts = [&](int buf) {
        // A: a0=(r0,kp0) a1=(r1,kp0) a2=(r0,kp1) a3=(r1,kp1)
        uint32_t ahi[4], alo[4];
        ahi[0] = pack2(av[0][0], av[0][1]);
        ahi[1] = pack2(av[0][2], av[0][3]);
        ahi[2] = pack2(av[1][0], av[1][1]);
        ahi[3] = pack2(av[1][2], av[1][3]);
        alo[0] = pack2(av[0][0] - lo_f(ahi[0]), av[0][1] - hi_f(ahi[0]));
        alo[1] = pack2(av[0][2] - lo_f(ahi[1]), av[0][3] - hi_f(ahi[1]));
        alo[2] = pack2(av[1][0] - lo_f(ahi[2]), av[1][1] - hi_f(ahi[2]));
        alo[3] = pack2(av[1][2] - lo_f(ahi[3]), av[1][3] - hi_f(ahi[3]));
        *(uint4*)&sA[buf][((sg*2 + 0)*32 + lane)*4] = make_uint4(ahi[0],ahi[1],ahi[2],ahi[3]);
        *(uint4*)&sA[buf][((sg*2 + 1)*32 + lane)*4] = make_uint4(alo[0],alo[1],alo[2],alo[3]);
        #pragma unroll
        for (int i = 0; i < NBS; i++) {
            int s = tx + i*256;
            if (s < 4*BN) {
                int tg = s / BN, c = s - tg*BN;
                uint32_t bh0 = pack2(bv[i][0], bv[i][1]);
                uint32_t bh1 = pack2(bv[i][2], bv[i][3]);
                uint32_t bl0 = pack2(bv[i][0] - lo_f(bh0), bv[i][1] - hi_f(bh0));
                uint32_t bl1 = pack2(bv[i][2] - lo_f(bh1), bv[i][3] - hi_f(bh1));
                *(uint4*)&sB[buf][(tg*BNp + c)*4] = make_uint4(bh0, bh1, bl0, bl1);
            }
        }
    };

    auto compute = [&](int buf) {
        uint32_t ahi[2][4], alo[2][4];
        #pragma unroll
        for (int gi = 0; gi < 2; gi++) {
            int g = wm*2 + gi;
            uint4 h = *(const uint4*)&sA[buf][((g*2 + 0)*32 + lane)*4];
            uint4 l = *(const uint4*)&sA[buf][((g*2 + 1)*32 + lane)*4];
            ahi[gi][0]=h.x; ahi[gi][1]=h.y; ahi[gi][2]=h.z; ahi[gi][3]=h.w;
            alo[gi][0]=l.x; alo[gi][1]=l.y; alo[gi][2]=l.z; alo[gi][3]=l.w;
        }
        #pragma unroll
        for (int nt = 0; nt < NT; nt++) {
            int nc = wc*WN + nt*8 + (lane >> 2);
            uint4 b4 = *(const uint4*)&sB[buf][((lane & 3)*BNp + nc)*4];
            uint32_t bhi[2] = {b4.x, b4.y};
            uint32_t blo[2] = {b4.z, b4.w};
            #pragma unroll
            for (int gi = 0; gi < 2; gi++) {
                mma_bf16(acc[gi][nt], ahi[gi], bhi);
                mma_bf16(acc[gi][nt], ahi[gi], blo);
                mma_bf16(acc[gi][nt], alo[gi], bhi);
            }
        }
    };

    // ---- prologue ----
    load_regs(0);
    cvt_sts(0);
    if (nk > 1) load_regs(1);
    __syncthreads();

    for (int kt = 0; kt < nk; kt++) {
        compute(kt & 1);
        if (kt + 1 < nk) {
            cvt_sts((kt + 1) & 1);
            __syncthreads();
            if (kt + 2 < nk) load_regs(kt + 2);
        }
    }

    // ---- epilogue ----
    #pragma unroll
    for (int gi = 0; gi < 2; gi++) {
        int gr0 = row0 + (wm*2 + gi)*16 + (lane >> 2);
        int gr1 = gr0 + 8;
        #pragma unroll
        for (int nt = 0; nt < NT; nt++) {
            int gc = col0 + wc*WN + nt*8 + (lane & 3)*2;
            if (gr0 < M)
                *(float2*)&C[(long)gr0*N + gc] = make_float2(acc[gi][nt][0], acc[gi][nt][1]);
            if (gr1 < M)
                *(float2*)&C[(long)gr1*N + gc] = make_float2(acc[gi][nt][2], acc[gi][nt][3]);
        }
    }
}

// ---------------- attention scores ----------------
template<int H, int C>
__global__ void attn_kernel(const float* __restrict__ h,
                            const float* __restrict__ att_s,
                            const float* __restrict__ att_d,
                            float* __restrict__ as_out,
                            float* __restrict__ ad_out, int N)
{
    int t = blockIdx.x*blockDim.x + threadIdx.x;
    if (t >= N*H) return;
    int hh = t % H;
    const float* hp = h + (long)t * C;
    const float* sp = att_s + hh*C;
    const float* dp = att_d + hh*C;
    float s = 0.f, d = 0.f;
    #pragma unroll
    for (int c = 0; c < C; c += 4) {
        float4 hv = *(const float4*)&hp[c];
        float4 sv = *(const float4*)&sp[c];
        float4 dv = *(const float4*)&dp[c];
        s = fmaf(hv.x,sv.x, fmaf(hv.y,sv.y, fmaf(hv.z,sv.z, fmaf(hv.w,sv.w, s))));
        d = fmaf(hv.x,dv.x, fmaf(hv.y,dv.y, fmaf(hv.z,dv.z, fmaf(hv.w,dv.w, d))));
    }
    as_out[t] = s;
    ad_out[t] = d;
}

// ---------------- per-dst-node softmax aggregation (one warp / node) --------
template<int H, int C>
__global__ void agg_kernel(const float* __restrict__ h,
                           const float* __restrict__ as_in,
                           const float* __restrict__ ad_in,
                           const float* __restrict__ bias,
                           float* __restrict__ out, int N)
{
    constexpr int CH = H*C;
    constexpr int J  = CH/32;
    int warp = (blockIdx.x*blockDim.x + threadIdx.x) >> 5;
    int lane = threadIdx.x & 31;
    if (warp >= N) return;
    const int v = warp;

    float adv = (lane < H) ? ad_in[v*H + lane] : 0.f;
    int b = g_offs[v], e = g_offs[v+1];

    float den = 0.f;
    float acc[J];
    #pragma unroll
    for (int j = 0; j < J; j++) acc[j] = 0.f;

    if (b < e) {
        int s = g_srcs[b];
        for (int i = b; i < e; i++) {
            int s_next = (i+1 < e) ? g_srcs[i+1] : s;
            float ex = 0.f;
            if (lane < H) {
                float ev = as_in[s*H + lane] + adv;
                ev = (ev > 0.f) ? ev : 0.2f*ev;
                ex = __expf(ev);
                den += ex;
            }
            const float* hp = h + (long)s*CH;
            #pragma unroll
            for (int j = 0; j < J; j++) {
                int ch = lane + 32*j;
                float exh = __shfl_sync(0xffffffffu, ex, ch / C);
                acc[j] = fmaf(exh, hp[ch], acc[j]);
            }
            s = s_next;
        }
    }
    #pragma unroll
    for (int j = 0; j < J; j++) {
        int ch = lane + 32*j;
        float dh = __shfl_sync(0xffffffffu, den, ch / C);
        float o = acc[j]/dh + bias[ch];
        o = (o > 0.f) ? o : expm1f(o);
        out[(long)v*CH + ch] = o;
    }
}

// ---------------- pair head ----------------
__global__ void pair_kernel(const float* __restrict__ x2,
                            const int* __restrict__ n1,
                            const int* __restrict__ n2,
                            const float* __restrict__ linW,
                            const float* __restrict__ linb,
                            float* __restrict__ y, int P)
{
    int p = blockIdx.x*blockDim.x + threadIdx.x;
    if (p >= P) return;
    const float* a  = x2 + (long)n1[p]*CH2;
    const float* bb = x2 + (long)n2[p]*CH2;
    float y0 = linb[0], y1 = linb[1];
    #pragma unroll
    for (int j = 0; j < CH2; j++) {
        float v = a[j];
        y0 = fmaf(v, linW[j*2],   y0);
        y1 = fmaf(v, linW[j*2+1], y1);
    }
    #pragma unroll
    for (int j = 0; j < CH2; j++) {
        float v = bb[j];
        y0 = fmaf(v, linW[(CH2+j)*2],   y0);
        y1 = fmaf(v, linW[(CH2+j)*2+1], y1);
    }
    y[p*2]   = 1.f/(1.f + __expf(-y0));
    y[p*2+1] = 1.f/(1.f + __expf(-y1));
}

// ---------------- launch ----------------
extern "C" void kernel_launch(void* const* d_in, const int* in_sizes, int n_in,
                              void* d_out, int out_size)
{
    const float* features = (const float*)d_in[0];
    const int*   eidx     = (const int*)  d_in[1];
    const int*   n1idx    = (const int*)  d_in[2];
    const int*   n2idx    = (const int*)  d_in[3];
    const float* W1       = (const float*)d_in[4];
    const float* attS1    = (const float*)d_in[5];
    const float* attD1    = (const float*)d_in[6];
    const float* b1       = (const float*)d_in[7];
    const float* W2       = (const float*)d_in[8];
    const float* attS2    = (const float*)d_in[9];
    const float* attD2    = (const float*)d_in[10];
    const float* b2       = (const float*)d_in[11];
    const float* linW     = (const float*)d_in[12];
    const float* linb     = (const float*)d_in[13];

    const int N = N_NODES;
    const int E = in_sizes[1] / 2;
    const int P = in_sizes[2];
    const int etot = E + N;
    const int* srcE = eidx;
    const int* dstE = eidx + E;

    float* y_out  = (float*)d_out;          // [P,2]
    float* x2_out = y_out + (long)P*2;      // [N,64]

    float *p_h1, *p_x1, *p_h2, *p_as1, *p_ad1, *p_as2, *p_ad2;
    cudaGetSymbolAddress((void**)&p_h1,  g_h1);
    cudaGetSymbolAddress((void**)&p_x1,  g_x1);
    cudaGetSymbolAddress((void**)&p_h2,  g_h2);
    cudaGetSymbolAddress((void**)&p_as1, g_as1);
    cudaGetSymbolAddress((void**)&p_ad1, g_ad1);
    cudaGetSymbolAddress((void**)&p_as2, g_as2);
    cudaGetSymbolAddress((void**)&p_ad2, g_ad2);

    // ---- CSR build; gemm1 kept as 4th launch for the ncu sample ----
    zero_kernel<<<(N+255)/256, 256>>>(N);
    count_kernel<<<(etot+255)/256, 256>>>(dstE, E, N);
    int nb = (N + 1023) / 1024;
    scan1_kernel<<<nb, 1024>>>(N);
    {
        dim3 grid((N + 127)/128, CH1/96);
        gemm_tc_kernel<96><<<grid, 256>>>(features, W1, p_h1, N, CH1, NUM_FEA);
    }
    scan2_kernel<<<1, 64>>>(nb);
    scan3_kernel<<<(N+255)/256, 256>>>(N);
    scatter_kernel<<<(etot+255)/256, 256>>>(srcE, dstE, E, N);

    // ---- layer 1 ----
    attn_kernel<HEAD1, HID1><<<(N*HEAD1 + 255)/256, 256>>>(p_h1, attS1, attD1, p_as1, p_ad1, N);
    agg_kernel<HEAD1, HID1><<<(N*32 + 255)/256, 256>>>(p_h1, p_as1, p_ad1, b1, p_x1, N);

    // ---- layer 2 ----
    {
        dim3 grid((N + 127)/128, 1);
        gemm_tc_kernel<64><<<grid, 256>>>(p_x1, W2, p_h2, N, CH2, CH1);
    }
    attn_kernel<HEAD2, HID2><<<(N*HEAD2 + 255)/256, 256>>>(p_h2, attS2, attD2, p_as2, p_ad2, N);
    agg_kernel<HEAD2, HID2><<<(N*32 + 255)/256, 256>>>(p_h2, p_as2, p_ad2, b2, x2_out, N);

    // ---- pair head ----
    pair_kernel<<<(P+255)/256, 256>>>(x2_out, n1idx, n2idx, linW, linb, y_out, P);
}

// round 9
// speedup vs baseline: 2.3871x; 1.0998x over previous
#include <cuda_runtime.h>
#include <math.h>
#include <stdint.h>

// ---------------- problem constants ----------------
#define N_NODES 50000
#define NUM_FEA 213
#define HID1 16
#define HEAD1 12
#define CH1 (HID1*HEAD1)   // 192
#define HID2 8
#define HEAD2 8
#define CH2 (HID2*HEAD2)   // 64
#define E_EDGES 800000
#define E_TOT (E_EDGES + N_NODES)

// ---------------- device scratch ----------------
static __device__ float g_h1[N_NODES*CH1];
static __device__ float g_x1[N_NODES*CH1];
static __device__ float g_h2[N_NODES*CH2];
static __device__ float g_as1[N_NODES*HEAD1];
static __device__ float g_ad1[N_NODES*HEAD1];
static __device__ float g_as2[N_NODES*HEAD2];
static __device__ float g_ad2[N_NODES*HEAD2];
static __device__ int   g_deg[N_NODES];
static __device__ int   g_cur[N_NODES];
static __device__ int   g_tmp[N_NODES];
static __device__ int   g_offs[N_NODES+1];
static __device__ int   g_bsum[64];
static __device__ int   g_srcs[E_TOT];

// ---------------- CSR build ----------------
__global__ void zero_kernel(int n)
{
    int i = blockIdx.x*blockDim.x + threadIdx.x;
    if (i < n) { g_deg[i] = 0; g_cur[i] = 0; }
}

__global__ void count_kernel(const int* __restrict__ dstE, int E, int n)
{
    int i = blockIdx.x*blockDim.x + threadIdx.x;
    int tot = E + n;
    if (i >= tot) return;
    int d = (i < E) ? dstE[i] : (i - E);
    atomicAdd(&g_deg[d], 1);
}

__global__ void scan1_kernel(int n)
{
    __shared__ int sh[1024];
    int t = threadIdx.x;
    int i = blockIdx.x*1024 + t;
    sh[t] = (i < n) ? g_deg[i] : 0;
    __syncthreads();
    #pragma unroll
    for (int off = 1; off < 1024; off <<= 1) {
        int v = 0;
        if (t >= off) v = sh[t-off];
        __syncthreads();
        sh[t] += v;
        __syncthreads();
    }
    if (i < n) g_tmp[i] = sh[t];
    if (t == 1023) g_bsum[blockIdx.x] = sh[1023];
}

__global__ void scan2_kernel(int nb)
{
    __shared__ int sh[64];
    int t = threadIdx.x;
    int mine = (t < nb) ? g_bsum[t] : 0;
    sh[t] = mine;
    __syncthreads();
    #pragma unroll
    for (int off = 1; off < 64; off <<= 1) {
        int v = (t >= off) ? sh[t-off] : 0;
        __syncthreads();
        sh[t] += v;
        __syncthreads();
    }
    if (t < nb) g_bsum[t] = sh[t] - mine;
}

__global__ void scan3_kernel(int n)
{
    int i = blockIdx.x*blockDim.x + threadIdx.x;
    if (i < n) g_offs[i+1] = g_tmp[i] + g_bsum[i >> 10];
    if (i == 0) g_offs[0] = 0;
}

__global__ void scatter_kernel(const int* __restrict__ srcE,
                               const int* __restrict__ dstE, int E, int n)
{
    int i = blockIdx.x*blockDim.x + threadIdx.x;
    int tot = E + n;
    if (i >= tot) return;
    int s, d;
    if (i < E) { s = srcE[i]; d = dstE[i]; }
    else       { s = d = i - E; }
    int pos = g_offs[d] + atomicAdd(&g_cur[d], 1);
    g_srcs[pos] = s;
}

// ---------------- 3x-bf16 tensor-core GEMM (m16n8k16), double-buffered -----
__device__ __forceinline__ uint32_t pack2(float v0, float v1)   // lo16=bf(v0), hi16=bf(v1)
{
    uint32_t d;
    asm("cvt.rn.bf16x2.f32 %0, %1, %2;" : "=r"(d) : "f"(v1), "f"(v0));
    return d;
}
__device__ __forceinline__ float lo_f(uint32_t d) { return __uint_as_float(d << 16); }
__device__ __forceinline__ float hi_f(uint32_t d) { return __uint_as_float(d & 0xffff0000u); }

__device__ __forceinline__ void mma_bf16(float* d, const uint32_t* a, const uint32_t* b)
{
    asm volatile("mma.sync.aligned.m16n8k16.row.col.f32.bf16.bf16.f32 "
                 "{%0,%1,%2,%3}, {%4,%5,%6,%7}, {%8,%9}, {%0,%1,%2,%3};"
                 : "+f"(d[0]), "+f"(d[1]), "+f"(d[2]), "+f"(d[3])
                 : "r"(a[0]), "r"(a[1]), "r"(a[2]), "r"(a[3]),
                   "r"(b[0]), "r"(b[1]));
}

template<int BN>
__global__ __launch_bounds__(256, 2)
void gemm_tc_kernel(const float* __restrict__ A,
                    const float* __restrict__ B,
                    float* __restrict__ C,
                    int M, int N, int K)
{
    constexpr int BM = 128, BK = 16;
    constexpr int BNp = BN + 2;
    constexpr int WN = BN/2;
    constexpr int NT = WN/8;
    constexpr int NBS = (4*BN + 255)/256;
    constexpr int ASZ = 8*2*32*4;
    constexpr int BSZ = 4*BNp*4;

    __shared__ uint32_t sA[2][ASZ];
    __shared__ uint32_t sB[2][BSZ];

    const int tx   = threadIdx.x;
    const int lane = tx & 31;
    const int wid  = tx >> 5;
    const int wm   = wid & 3;
    const int wc   = wid >> 2;

    const int row0 = blockIdx.x * BM;
    const int col0 = blockIdx.y * BN;

    const int sg  = tx >> 5;
    const int srr = lane >> 2;
    const int scc = lane & 3;

    const int r0g = row0 + sg*16 + srr;
    const int r1g = r0g + 8;
    const bool r0ok = r0g < M, r1ok = r1g < M;
    const long r0a = (long)(r0ok ? r0g : 0) * K;
    const long r1a = (long)(r1ok ? r1g : 0) * K;

    float av[2][4];
    float bv[NBS][4];

    float acc[2][NT][4];
    #pragma unroll
    for (int gi = 0; gi < 2; gi++)
        #pragma unroll
        for (int nt = 0; nt < NT; nt++)
            #pragma unroll
            for (int j = 0; j < 4; j++) acc[gi][nt][j] = 0.f;

    const int nk = (K + BK - 1) / BK;

    auto load_regs = [&](int kt) {
        const int k0 = kt * BK;
        #pragma unroll
        for (int p = 0; p < 2; p++) {
            int kq = k0 + 2*scc + 8*p;
            bool k0ok = kq < K, k1ok = (kq+1) < K;
            av[p][0] = (r0ok && k0ok) ? A[r0a + kq]     : 0.f;
            av[p][1] = (r0ok && k1ok) ? A[r0a + kq + 1] : 0.f;
            av[p][2] = (r1ok && k0ok) ? A[r1a + kq]     : 0.f;
            av[p][3] = (r1ok && k1ok) ? A[r1a + kq + 1] : 0.f;
        }
        #pragma unroll
        for (int i = 0; i < NBS; i++) {
            int s = tx + i*256;
            if (s < 4*BN) {
                int tg = s / BN, c = s - tg*BN;
                int k = k0 + 2*tg;
                bv[i][0] = (k   < K) ? B[(long)k*N     + col0 + c] : 0.f;
                bv[i][1] = (k+1 < K) ? B[(long)(k+1)*N + col0 + c] : 0.f;
                bv[i][2] = (k+8 < K) ? B[(long)(k+8)*N + col0 + c] : 0.f;
                bv[i][3] = (k+9 < K) ? B[(long)(k+9)*N + col0 + c] : 0.f;
            }
        }
    };

    auto cvt_sts = [&](int buf) {
        uint32_t ahi[4], alo[4];
        ahi[0] = pack2(av[0][0], av[0][1]);
        ahi[1] = pack2(av[0][2], av[0][3]);
        ahi[2] = pack2(av[1][0], av[1][1]);
        ahi[3] = pack2(av[1][2], av[1][3]);
        alo[0] = pack2(av[0][0] - lo_f(ahi[0]), av[0][1] - hi_f(ahi[0]));
        alo[1] = pack2(av[0][2] - lo_f(ahi[1]), av[0][3] - hi_f(ahi[1]));
        alo[2] = pack2(av[1][0] - lo_f(ahi[2]), av[1][1] - hi_f(ahi[2]));
        alo[3] = pack2(av[1][2] - lo_f(ahi[3]), av[1][3] - hi_f(ahi[3]));
        *(uint4*)&sA[buf][((sg*2 + 0)*32 + lane)*4] = make_uint4(ahi[0],ahi[1],ahi[2],ahi[3]);
        *(uint4*)&sA[buf][((sg*2 + 1)*32 + lane)*4] = make_uint4(alo[0],alo[1],alo[2],alo[3]);
        #pragma unroll
        for (int i = 0; i < NBS; i++) {
            int s = tx + i*256;
            if (s < 4*BN) {
                int tg = s / BN, c = s - tg*BN;
                uint32_t bh0 = pack2(bv[i][0], bv[i][1]);
                uint32_t bh1 = pack2(bv[i][2], bv[i][3]);
                uint32_t bl0 = pack2(bv[i][0] - lo_f(bh0), bv[i][1] - hi_f(bh0));
                uint32_t bl1 = pack2(bv[i][2] - lo_f(bh1), bv[i][3] - hi_f(bh1));
                *(uint4*)&sB[buf][(tg*BNp + c)*4] = make_uint4(bh0, bh1, bl0, bl1);
            }
        }
    };

    auto compute = [&](int buf) {
        uint32_t ahi[2][4], alo[2][4];
        #pragma unroll
        for (int gi = 0; gi < 2; gi++) {
            int g = wm*2 + gi;
            uint4 h = *(const uint4*)&sA[buf][((g*2 + 0)*32 + lane)*4];
            uint4 l = *(const uint4*)&sA[buf][((g*2 + 1)*32 + lane)*4];
            ahi[gi][0]=h.x; ahi[gi][1]=h.y; ahi[gi][2]=h.z; ahi[gi][3]=h.w;
            alo[gi][0]=l.x; alo[gi][1]=l.y; alo[gi][2]=l.z; alo[gi][3]=l.w;
        }
        #pragma unroll
        for (int nt = 0; nt < NT; nt++) {
            int nc = wc*WN + nt*8 + (lane >> 2);
            uint4 b4 = *(const uint4*)&sB[buf][((lane & 3)*BNp + nc)*4];
            uint32_t bhi[2] = {b4.x, b4.y};
            uint32_t blo[2] = {b4.z, b4.w};
            #pragma unroll
            for (int gi = 0; gi < 2; gi++) {
                mma_bf16(acc[gi][nt], ahi[gi], bhi);
                mma_bf16(acc[gi][nt], ahi[gi], blo);
                mma_bf16(acc[gi][nt], alo[gi], bhi);
            }
        }
    };

    load_regs(0);
    cvt_sts(0);
    if (nk > 1) load_regs(1);
    __syncthreads();

    for (int kt = 0; kt < nk; kt++) {
        compute(kt & 1);
        if (kt + 1 < nk) {
            cvt_sts((kt + 1) & 1);
            __syncthreads();
            if (kt + 2 < nk) load_regs(kt + 2);
        }
    }

    #pragma unroll
    for (int gi = 0; gi < 2; gi++) {
        int gr0 = row0 + (wm*2 + gi)*16 + (lane >> 2);
        int gr1 = gr0 + 8;
        #pragma unroll
        for (int nt = 0; nt < NT; nt++) {
            int gc = col0 + wc*WN + nt*8 + (lane & 3)*2;
            if (gr0 < M)
                *(float2*)&C[(long)gr0*N + gc] = make_float2(acc[gi][nt][0], acc[gi][nt][1]);
            if (gr1 < M)
                *(float2*)&C[(long)gr1*N + gc] = make_float2(acc[gi][nt][2], acc[gi][nt][3]);
        }
    }
}

// ---------------- attention scores ----------------
template<int H, int C>
__global__ void attn_kernel(const float* __restrict__ h,
                            const float* __restrict__ att_s,
                            const float* __restrict__ att_d,
                            float* __restrict__ as_out,
                            float* __restrict__ ad_out, int N)
{
    int t = blockIdx.x*blockDim.x + threadIdx.x;
    if (t >= N*H) return;
    int hh = t % H;
    const float* hp = h + (long)t * C;
    const float* sp = att_s + hh*C;
    const float* dp = att_d + hh*C;
    float s = 0.f, d = 0.f;
    #pragma unroll
    for (int c = 0; c < C; c += 4) {
        float4 hv = *(const float4*)&hp[c];
        float4 sv = *(const float4*)&sp[c];
        float4 dv = *(const float4*)&dp[c];
        s = fmaf(hv.x,sv.x, fmaf(hv.y,sv.y, fmaf(hv.z,sv.z, fmaf(hv.w,sv.w, s))));
        d = fmaf(hv.x,dv.x, fmaf(hv.y,dv.y, fmaf(hv.z,dv.z, fmaf(hv.w,dv.w, d))));
    }
    as_out[t] = s;
    ad_out[t] = d;
}

// ---------------- per-dst-node softmax aggregation (one warp / node) --------
// Vectorized channel walk: NFULL float4 iters (all lanes) + float2 remainder.
// 4-aligned (and 2-aligned) channel blocks never cross a C-wide head boundary.
template<int H, int C>
__global__ void agg_kernel(const float* __restrict__ h,
                           const float* __restrict__ as_in,
                           const float* __restrict__ ad_in,
                           const float* __restrict__ bias,
                           float* __restrict__ out, int N)
{
    constexpr int CH = H*C;
    constexpr int NFULL = CH/128;                 // float4 iters: 1 (192) / 0 (64)
    constexpr bool HASREM = (CH % 128) != 0;      // 64-wide float2 remainder
    int warp = (blockIdx.x*blockDim.x + threadIdx.x) >> 5;
    int lane = threadIdx.x & 31;
    if (warp >= N) return;
    const int v = warp;

    float adv = (lane < H) ? ad_in[v*H + lane] : 0.f;
    int b = g_offs[v], e = g_offs[v+1];

    // per-lane head indices (constant across edges)
    int headF[NFULL > 0 ? NFULL : 1];
    #pragma unroll
    for (int j = 0; j < NFULL; j++) headF[j] = (j*128 + 4*lane) / C;
    const int headR = (NFULL*128 + 2*lane) / C;

    float den = 0.f;
    float4 accF[NFULL > 0 ? NFULL : 1];
    #pragma unroll
    for (int j = 0; j < NFULL; j++) accF[j] = make_float4(0.f,0.f,0.f,0.f);
    float2 accR = make_float2(0.f, 0.f);

    if (b < e) {
        int s = g_srcs[b];
        for (int i = b; i < e; i++) {
            int s_next = (i+1 < e) ? g_srcs[i+1] : s;
            float ex = 0.f;
            if (lane < H) {
                float ev = as_in[s*H + lane] + adv;
                ev = (ev > 0.f) ? ev : 0.2f*ev;
                ex = __expf(ev);
                den += ex;
            }
            const float* hp = h + (long)s*CH;
            #pragma unroll
            for (int j = 0; j < NFULL; j++) {
                float4 hv = *(const float4*)&hp[j*128 + 4*lane];
                float exh = __shfl_sync(0xffffffffu, ex, headF[j]);
                accF[j].x = fmaf(exh, hv.x, accF[j].x);
                accF[j].y = fmaf(exh, hv.y, accF[j].y);
                accF[j].z = fmaf(exh, hv.z, accF[j].z);
                accF[j].w = fmaf(exh, hv.w, accF[j].w);
            }
            if (HASREM) {
                float2 hv = *(const float2*)&hp[NFULL*128 + 2*lane];
                float exh = __shfl_sync(0xffffffffu, ex, headR);
                accR.x = fmaf(exh, hv.x, accR.x);
                accR.y = fmaf(exh, hv.y, accR.y);
            }
            s = s_next;
        }
    }

    #pragma unroll
    for (int j = 0; j < NFULL; j++) {
        float dh = __shfl_sync(0xffffffffu, den, headF[j]);
        float4 bb = *(const float4*)&bias[j*128 + 4*lane];
        float4 o;
        o.x = accF[j].x/dh + bb.x;  o.x = (o.x > 0.f) ? o.x : expm1f(o.x);
        o.y = accF[j].y/dh + bb.y;  o.y = (o.y > 0.f) ? o.y : expm1f(o.y);
        o.z = accF[j].z/dh + bb.z;  o.z = (o.z > 0.f) ? o.z : expm1f(o.z);
        o.w = accF[j].w/dh + bb.w;  o.w = (o.w > 0.f) ? o.w : expm1f(o.w);
        *(float4*)&out[(long)v*CH + j*128 + 4*lane] = o;
    }
    if (HASREM) {
        float dh = __shfl_sync(0xffffffffu, den, headR);
        float2 bb = *(const float2*)&bias[NFULL*128 + 2*lane];
        float2 o;
        o.x = accR.x/dh + bb.x;  o.x = (o.x > 0.f) ? o.x : expm1f(o.x);
        o.y = accR.y/dh + bb.y;  o.y = (o.y > 0.f) ? o.y : expm1f(o.y);
        *(float2*)&out[(long)v*CH + NFULL*128 + 2*lane] = o;
    }
}

// ---------------- pair head ----------------
__global__ void pair_kernel(const float* __restrict__ x2,
                            const int* __restrict__ n1,
                            const int* __restrict__ n2,
                            const float* __restrict__ linW,
                            const float* __restrict__ linb,
                            float* __restrict__ y, int P)
{
    int p = blockIdx.x*blockDim.x + threadIdx.x;
    if (p >= P) return;
    const float* a  = x2 + (long)n1[p]*CH2;
    const float* bb = x2 + (long)n2[p]*CH2;
    float y0 = linb[0], y1 = linb[1];
    #pragma unroll
    for (int j = 0; j < CH2; j++) {
        float v = a[j];
        y0 = fmaf(v, linW[j*2],   y0);
        y1 = fmaf(v, linW[j*2+1], y1);
    }
    #pragma unroll
    for (int j = 0; j < CH2; j++) {
        float v = bb[j];
        y0 = fmaf(v, linW[(CH2+j)*2],   y0);
        y1 = fmaf(v, linW[(CH2+j)*2+1], y1);
    }
    y[p*2]   = 1.f/(1.f + __expf(-y0));
    y[p*2+1] = 1.f/(1.f + __expf(-y1));
}

// ---------------- launch ----------------
extern "C" void kernel_launch(void* const* d_in, const int* in_sizes, int n_in,
                              void* d_out, int out_size)
{
    const float* features = (const float*)d_in[0];
    const int*   eidx     = (const int*)  d_in[1];
    const int*   n1idx    = (const int*)  d_in[2];
    const int*   n2idx    = (const int*)  d_in[3];
    const float* W1       = (const float*)d_in[4];
    const float* attS1    = (const float*)d_in[5];
    const float* attD1    = (const float*)d_in[6];
    const float* b1       = (const float*)d_in[7];
    const float* W2       = (const float*)d_in[8];
    const float* attS2    = (const float*)d_in[9];
    const float* attD2    = (const float*)d_in[10];
    const float* b2       = (const float*)d_in[11];
    const float* linW     = (const float*)d_in[12];
    const float* linb     = (const float*)d_in[13];

    const int N = N_NODES;
    const int E = in_sizes[1] / 2;
    const int P = in_sizes[2];
    const int etot = E + N;
    const int* srcE = eidx;
    const int* dstE = eidx + E;

    float* y_out  = (float*)d_out;          // [P,2]
    float* x2_out = y_out + (long)P*2;      // [N,64]

    float *p_h1, *p_x1, *p_h2, *p_as1, *p_ad1, *p_as2, *p_ad2;
    cudaGetSymbolAddress((void**)&p_h1,  g_h1);
    cudaGetSymbolAddress((void**)&p_x1,  g_x1);
    cudaGetSymbolAddress((void**)&p_h2,  g_h2);
    cudaGetSymbolAddress((void**)&p_as1, g_as1);
    cudaGetSymbolAddress((void**)&p_ad1, g_ad1);
    cudaGetSymbolAddress((void**)&p_as2, g_as2);
    cudaGetSymbolAddress((void**)&p_ad2, g_ad2);

    // ---- CSR build; gemm1 kept as 4th launch for the ncu sample ----
    zero_kernel<<<(N+255)/256, 256>>>(N);
    count_kernel<<<(etot+255)/256, 256>>>(dstE, E, N);
    int nb = (N + 1023) / 1024;
    scan1_kernel<<<nb, 1024>>>(N);
    {
        dim3 grid((N + 127)/128, CH1/96);
        gemm_tc_kernel<96><<<grid, 256>>>(features, W1, p_h1, N, CH1, NUM_FEA);
    }
    scan2_kernel<<<1, 64>>>(nb);
    scan3_kernel<<<(N+255)/256, 256>>>(N);
    scatter_kernel<<<(etot+255)/256, 256>>>(srcE, dstE, E, N);

    // ---- layer 1 ----
    attn_kernel<HEAD1, HID1><<<(N*HEAD1 + 255)/256, 256>>>(p_h1, attS1, attD1, p_as1, p_ad1, N);
    agg_kernel<HEAD1, HID1><<<(N*32 + 255)/256, 256>>>(p_h1, p_as1, p_ad1, b1, p_x1, N);

    // ---- layer 2 ----
    {
        dim3 grid((N + 127)/128, 1);
        gemm_tc_kernel<64><<<grid, 256>>>(p_x1, W2, p_h2, N, CH2, CH1);
    }
    attn_kernel<HEAD2, HID2><<<(N*HEAD2 + 255)/256, 256>>>(p_h2, attS2, attD2, p_as2, p_ad2, N);
    agg_kernel<HEAD2, HID2><<<(N*32 + 255)/256, 256>>>(p_h2, p_as2, p_ad2, b2, x2_out, N);

    // ---- pair head ----
    pair_kernel<<<(P+255)/256, 256>>>(x2_out, n1idx, n2idx, linW, linb, y_out, P);
}

// round 10
// speedup vs baseline: 2.4400x; 1.0222x over previous
#include <cuda_runtime.h>
#include <math.h>
#include <stdint.h>

// ---------------- problem constants ----------------
#define N_NODES 50000
#define NUM_FEA 213
#define HID1 16
#define HEAD1 12
#define CH1 (HID1*HEAD1)   // 192
#define HID2 8
#define HEAD2 8
#define CH2 (HID2*HEAD2)   // 64
#define E_EDGES 800000
#define E_TOT (E_EDGES + N_NODES)

// ---------------- device scratch ----------------
static __device__ float g_h1[N_NODES*CH1];
static __device__ float g_x1[N_NODES*CH1];
static __device__ float g_h2[N_NODES*CH2];
static __device__ float g_as1[N_NODES*HEAD1];
static __device__ float g_ad1[N_NODES*HEAD1];
static __device__ float g_as2[N_NODES*HEAD2];
static __device__ float g_ad2[N_NODES*HEAD2];
static __device__ int   g_deg[N_NODES];
static __device__ int   g_cur[N_NODES];
static __device__ int   g_tmp[N_NODES];
static __device__ int   g_offs[N_NODES+1];
static __device__ int   g_bsum[64];
static __device__ int   g_srcs[E_TOT];

// ---------------- CSR build ----------------
__global__ void zero_kernel(int n)
{
    int i = blockIdx.x*blockDim.x + threadIdx.x;
    if (i < n) { g_deg[i] = 0; g_cur[i] = 0; }
}

__global__ void count_kernel(const int* __restrict__ dstE, int E, int n)
{
    int i = blockIdx.x*blockDim.x + threadIdx.x;
    int tot = E + n;
    if (i >= tot) return;
    int d = (i < E) ? dstE[i] : (i - E);
    atomicAdd(&g_deg[d], 1);
}

__global__ void scan1_kernel(int n)
{
    __shared__ int sh[1024];
    int t = threadIdx.x;
    int i = blockIdx.x*1024 + t;
    sh[t] = (i < n) ? g_deg[i] : 0;
    __syncthreads();
    #pragma unroll
    for (int off = 1; off < 1024; off <<= 1) {
        int v = 0;
        if (t >= off) v = sh[t-off];
        __syncthreads();
        sh[t] += v;
        __syncthreads();
    }
    if (i < n) g_tmp[i] = sh[t];
    if (t == 1023) g_bsum[blockIdx.x] = sh[1023];
}

__global__ void scan2_kernel(int nb)
{
    __shared__ int sh[64];
    int t = threadIdx.x;
    int mine = (t < nb) ? g_bsum[t] : 0;
    sh[t] = mine;
    __syncthreads();
    #pragma unroll
    for (int off = 1; off < 64; off <<= 1) {
        int v = (t >= off) ? sh[t-off] : 0;
        __syncthreads();
        sh[t] += v;
        __syncthreads();
    }
    if (t < nb) g_bsum[t] = sh[t] - mine;
}

__global__ void scan3_kernel(int n)
{
    int i = blockIdx.x*blockDim.x + threadIdx.x;
    if (i < n) g_offs[i+1] = g_tmp[i] + g_bsum[i >> 10];
    if (i == 0) g_offs[0] = 0;
}

__global__ void scatter_kernel(const int* __restrict__ srcE,
                               const int* __restrict__ dstE, int E, int n)
{
    int i = blockIdx.x*blockDim.x + threadIdx.x;
    int tot = E + n;
    if (i >= tot) return;
    int s, d;
    if (i < E) { s = srcE[i]; d = dstE[i]; }
    else       { s = d = i - E; }
    int pos = g_offs[d] + atomicAdd(&g_cur[d], 1);
    g_srcs[pos] = s;
}

// ---------------- 3x-bf16 tensor-core GEMM (m16n8k16), double-buffered -----
__device__ __forceinline__ uint32_t pack2(float v0, float v1)
{
    uint32_t d;
    asm("cvt.rn.bf16x2.f32 %0, %1, %2;" : "=r"(d) : "f"(v1), "f"(v0));
    return d;
}
__device__ __forceinline__ float lo_f(uint32_t d) { return __uint_as_float(d << 16); }
__device__ __forceinline__ float hi_f(uint32_t d) { return __uint_as_float(d & 0xffff0000u); }

__device__ __forceinline__ void mma_bf16(float* d, const uint32_t* a, const uint32_t* b)
{
    asm volatile("mma.sync.aligned.m16n8k16.row.col.f32.bf16.bf16.f32 "
                 "{%0,%1,%2,%3}, {%4,%5,%6,%7}, {%8,%9}, {%0,%1,%2,%3};"
                 : "+f"(d[0]), "+f"(d[1]), "+f"(d[2]), "+f"(d[3])
                 : "r"(a[0]), "r"(a[1]), "r"(a[2]), "r"(a[3]),
                   "r"(b[0]), "r"(b[1]));
}

template<int BN>
__global__ __launch_bounds__(256, 2)
void gemm_tc_kernel(const float* __restrict__ A,
                    const float* __restrict__ B,
                    float* __restrict__ C,
                    int M, int N, int K)
{
    constexpr int BM = 128, BK = 16;
    constexpr int BNp = BN + 2;
    constexpr int WN = BN/2;
    constexpr int NT = WN/8;
    constexpr int NBS = (4*BN + 255)/256;
    constexpr int ASZ = 8*2*32*4;
    constexpr int BSZ = 4*BNp*4;

    __shared__ uint32_t sA[2][ASZ];
    __shared__ uint32_t sB[2][BSZ];

    const int tx   = threadIdx.x;
    const int lane = tx & 31;
    const int wid  = tx >> 5;
    const int wm   = wid & 3;
    const int wc   = wid >> 2;

    const int row0 = blockIdx.x * BM;
    const int col0 = blockIdx.y * BN;

    const int sg  = tx >> 5;
    const int srr = lane >> 2;
    const int scc = lane & 3;

    const int r0g = row0 + sg*16 + srr;
    const int r1g = r0g + 8;
    const bool r0ok = r0g < M, r1ok = r1g < M;
    const long r0a = (long)(r0ok ? r0g : 0) * K;
    const long r1a = (long)(r1ok ? r1g : 0) * K;

    float av[2][4];
    float bv[NBS][4];

    float acc[2][NT][4];
    #pragma unroll
    for (int gi = 0; gi < 2; gi++)
        #pragma unroll
        for (int nt = 0; nt < NT; nt++)
            #pragma unroll
            for (int j = 0; j < 4; j++) acc[gi][nt][j] = 0.f;

    const int nk = (K + BK - 1) / BK;

    auto load_regs = [&](int kt) {
        const int k0 = kt * BK;
        #pragma unroll
        for (int p = 0; p < 2; p++) {
            int kq = k0 + 2*scc + 8*p;
            bool k0ok = kq < K, k1ok = (kq+1) < K;
            av[p][0] = (r0ok && k0ok) ? A[r0a + kq]     : 0.f;
            av[p][1] = (r0ok && k1ok) ? A[r0a + kq + 1] : 0.f;
            av[p][2] = (r1ok && k0ok) ? A[r1a + kq]     : 0.f;
            av[p][3] = (r1ok && k1ok) ? A[r1a + kq + 1] : 0.f;
        }
        #pragma unroll
        for (int i = 0; i < NBS; i++) {
            int s = tx + i*256;
            if (s < 4*BN) {
                int tg = s / BN, c = s - tg*BN;
                int k = k0 + 2*tg;
                bv[i][0] = (k   < K) ? B[(long)k*N     + col0 + c] : 0.f;
                bv[i][1] = (k+1 < K) ? B[(long)(k+1)*N + col0 + c] : 0.f;
                bv[i][2] = (k+8 < K) ? B[(long)(k+8)*N + col0 + c] : 0.f;
                bv[i][3] = (k+9 < K) ? B[(long)(k+9)*N + col0 + c] : 0.f;
            }
        }
    };

    auto cvt_sts = [&](int buf) {
        uint32_t ahi[4], alo[4];
        ahi[0] = pack2(av[0][0], av[0][1]);
        ahi[1] = pack2(av[0][2], av[0][3]);
        ahi[2] = pack2(av[1][0], av[1][1]);
        ahi[3] = pack2(av[1][2], av[1][3]);
        alo[0] = pack2(av[0][0] - lo_f(ahi[0]), av[0][1] - hi_f(ahi[0]));
        alo[1] = pack2(av[0][2] - lo_f(ahi[1]), av[0][3] - hi_f(ahi[1]));
        alo[2] = pack2(av[1][0] - lo_f(ahi[2]), av[1][1] - hi_f(ahi[2]));
        alo[3] = pack2(av[1][2] - lo_f(ahi[3]), av[1][3] - hi_f(ahi[3]));
        *(uint4*)&sA[buf][((sg*2 + 0)*32 + lane)*4] = make_uint4(ahi[0],ahi[1],ahi[2],ahi[3]);
        *(uint4*)&sA[buf][((sg*2 + 1)*32 + lane)*4] = make_uint4(alo[0],alo[1],alo[2],alo[3]);
        #pragma unroll
        for (int i = 0; i < NBS; i++) {
            int s = tx + i*256;
            if (s < 4*BN) {
                int tg = s / BN, c = s - tg*BN;
                uint32_t bh0 = pack2(bv[i][0], bv[i][1]);
                uint32_t bh1 = pack2(bv[i][2], bv[i][3]);
                uint32_t bl0 = pack2(bv[i][0] - lo_f(bh0), bv[i][1] - hi_f(bh0));
                uint32_t bl1 = pack2(bv[i][2] - lo_f(bh1), bv[i][3] - hi_f(bh1));
                *(uint4*)&sB[buf][(tg*BNp + c)*4] = make_uint4(bh0, bh1, bl0, bl1);
            }
        }
    };

    auto compute = [&](int buf) {
        uint32_t ahi[2][4], alo[2][4];
        #pragma unroll
        for (int gi = 0; gi < 2; gi++) {
            int g = wm*2 + gi;
            uint4 h = *(const uint4*)&sA[buf][((g*2 + 0)*32 + lane)*4];
            uint4 l = *(const uint4*)&sA[buf][((g*2 + 1)*32 + lane)*4];
            ahi[gi][0]=h.x; ahi[gi][1]=h.y; ahi[gi][2]=h.z; ahi[gi][3]=h.w;
            alo[gi][0]=l.x; alo[gi][1]=l.y; alo[gi][2]=l.z; alo[gi][3]=l.w;
        }
        #pragma unroll
        for (int nt = 0; nt < NT; nt++) {
            int nc = wc*WN + nt*8 + (lane >> 2);
            uint4 b4 = *(const uint4*)&sB[buf][((lane & 3)*BNp + nc)*4];
            uint32_t bhi[2] = {b4.x, b4.y};
            uint32_t blo[2] = {b4.z, b4.w};
            #pragma unroll
            for (int gi = 0; gi < 2; gi++) {
                mma_bf16(acc[gi][nt], ahi[gi], bhi);
                mma_bf16(acc[gi][nt], ahi[gi], blo);
                mma_bf16(acc[gi][nt], alo[gi], bhi);
            }
        }
    };

    load_regs(0);
    cvt_sts(0);
    if (nk > 1) load_regs(1);
    __syncthreads();

    for (int kt = 0; kt < nk; kt++) {
        compute(kt & 1);
        if (kt + 1 < nk) {
            cvt_sts((kt + 1) & 1);
            __syncthreads();
            if (kt + 2 < nk) load_regs(kt + 2);
        }
    }

    #pragma unroll
    for (int gi = 0; gi < 2; gi++) {
        int gr0 = row0 + (wm*2 + gi)*16 + (lane >> 2);
        int gr1 = gr0 + 8;
        #pragma unroll
        for (int nt = 0; nt < NT; nt++) {
            int gc = col0 + wc*WN + nt*8 + (lane & 3)*2;
            if (gr0 < M)
                *(float2*)&C[(long)gr0*N + gc] = make_float2(acc[gi][nt][0], acc[gi][nt][1]);
            if (gr1 < M)
                *(float2*)&C[(long)gr1*N + gc] = make_float2(acc[gi][nt][2], acc[gi][nt][3]);
        }
    }
}

// ---------------- attention scores ----------------
template<int H, int C>
__global__ void attn_kernel(const float* __restrict__ h,
                            const float* __restrict__ att_s,
                            const float* __restrict__ att_d,
                            float* __restrict__ as_out,
                            float* __restrict__ ad_out, int N)
{
    int t = blockIdx.x*blockDim.x + threadIdx.x;
    if (t >= N*H) return;
    int hh = t % H;
    const float* hp = h + (long)t * C;
    const float* sp = att_s + hh*C;
    const float* dp = att_d + hh*C;
    float s = 0.f, d = 0.f;
    #pragma unroll
    for (int c = 0; c < C; c += 4) {
        float4 hv = *(const float4*)&hp[c];
        float4 sv = *(const float4*)&sp[c];
        float4 dv = *(const float4*)&dp[c];
        s = fmaf(hv.x,sv.x, fmaf(hv.y,sv.y, fmaf(hv.z,sv.z, fmaf(hv.w,sv.w, s))));
        d = fmaf(hv.x,dv.x, fmaf(hv.y,dv.y, fmaf(hv.z,dv.z, fmaf(hv.w,dv.w, d))));
    }
    as_out[t] = s;
    ad_out[t] = d;
}

// ---------------- per-dst-node softmax aggregation, 2-edge unrolled --------
template<int H, int C>
__global__ void agg_kernel(const float* __restrict__ h,
                           const float* __restrict__ as_in,
                           const float* __restrict__ ad_in,
                           const float* __restrict__ bias,
                           float* __restrict__ out, int N)
{
    constexpr int CH = H*C;
    constexpr int NFULL = CH/128;
    constexpr bool HASREM = (CH % 128) != 0;
    int warp = (blockIdx.x*blockDim.x + threadIdx.x) >> 5;
    int lane = threadIdx.x & 31;
    if (warp >= N) return;
    const int v = warp;

    float adv = (lane < H) ? ad_in[v*H + lane] : 0.f;
    int b = g_offs[v], e = g_offs[v+1];

    int headF[NFULL > 0 ? NFULL : 1];
    #pragma unroll
    for (int j = 0; j < NFULL; j++) headF[j] = (j*128 + 4*lane) / C;
    const int headR = (NFULL*128 + 2*lane) / C;

    float den = 0.f;
    float4 accF[NFULL > 0 ? NFULL : 1];
    #pragma unroll
    for (int j = 0; j < NFULL; j++) accF[j] = make_float4(0.f,0.f,0.f,0.f);
    float2 accR = make_float2(0.f, 0.f);

    int i = b;
    for (; i + 1 < e; i += 2) {
        int s0 = g_srcs[i];
        int s1 = g_srcs[i+1];
        // issue both score loads, then both h loads, before consuming
        float ev0 = 0.f, ev1 = 0.f;
        if (lane < H) {
            ev0 = as_in[s0*H + lane];
            ev1 = as_in[s1*H + lane];
        }
        const float* hp0 = h + (long)s0*CH;
        const float* hp1 = h + (long)s1*CH;
        float4 hv0[NFULL > 0 ? NFULL : 1], hv1[NFULL > 0 ? NFULL : 1];
        float2 hr0, hr1;
        #pragma unroll
        for (int j = 0; j < NFULL; j++) {
            hv0[j] = *(const float4*)&hp0[j*128 + 4*lane];
            hv1[j] = *(const float4*)&hp1[j*128 + 4*lane];
        }
        if (HASREM) {
            hr0 = *(const float2*)&hp0[NFULL*128 + 2*lane];
            hr1 = *(const float2*)&hp1[NFULL*128 + 2*lane];
        }
        float ex0 = 0.f, ex1 = 0.f;
        if (lane < H) {
            float e0 = ev0 + adv; e0 = (e0 > 0.f) ? e0 : 0.2f*e0;
            float e1 = ev1 + adv; e1 = (e1 > 0.f) ? e1 : 0.2f*e1;
            ex0 = __expf(e0);
            ex1 = __expf(e1);
            den += ex0 + ex1;
        }
        #pragma unroll
        for (int j = 0; j < NFULL; j++) {
            float x0 = __shfl_sync(0xffffffffu, ex0, headF[j]);
            float x1 = __shfl_sync(0xffffffffu, ex1, headF[j]);
            accF[j].x = fmaf(x0, hv0[j].x, fmaf(x1, hv1[j].x, accF[j].x));
            accF[j].y = fmaf(x0, hv0[j].y, fmaf(x1, hv1[j].y, accF[j].y));
            accF[j].z = fmaf(x0, hv0[j].z, fmaf(x1, hv1[j].z, accF[j].z));
            accF[j].w = fmaf(x0, hv0[j].w, fmaf(x1, hv1[j].w, accF[j].w));
        }
        if (HASREM) {
            float x0 = __shfl_sync(0xffffffffu, ex0, headR);
            float x1 = __shfl_sync(0xffffffffu, ex1, headR);
            accR.x = fmaf(x0, hr0.x, fmaf(x1, hr1.x, accR.x));
            accR.y = fmaf(x0, hr0.y, fmaf(x1, hr1.y, accR.y));
        }
    }
    if (i < e) {   // tail edge
        int s = g_srcs[i];
        float ex = 0.f;
        if (lane < H) {
            float ev = as_in[s*H + lane] + adv;
            ev = (ev > 0.f) ? ev : 0.2f*ev;
            ex = __expf(ev);
            den += ex;
        }
        const float* hp = h + (long)s*CH;
        #pragma unroll
        for (int j = 0; j < NFULL; j++) {
            float4 hv = *(const float4*)&hp[j*128 + 4*lane];
            float exh = __shfl_sync(0xffffffffu, ex, headF[j]);
            accF[j].x = fmaf(exh, hv.x, accF[j].x);
            accF[j].y = fmaf(exh, hv.y, accF[j].y);
            accF[j].z = fmaf(exh, hv.z, accF[j].z);
            accF[j].w = fmaf(exh, hv.w, accF[j].w);
        }
        if (HASREM) {
            float2 hv = *(const float2*)&hp[NFULL*128 + 2*lane];
            float exh = __shfl_sync(0xffffffffu, ex, headR);
            accR.x = fmaf(exh, hv.x, accR.x);
            accR.y = fmaf(exh, hv.y, accR.y);
        }
    }

    #pragma unroll
    for (int j = 0; j < NFULL; j++) {
        float dh = __shfl_sync(0xffffffffu, den, headF[j]);
        float4 bb = *(const float4*)&bias[j*128 + 4*lane];
        float4 o;
        o.x = accF[j].x/dh + bb.x;  o.x = (o.x > 0.f) ? o.x : expm1f(o.x);
        o.y = accF[j].y/dh + bb.y;  o.y = (o.y > 0.f) ? o.y : expm1f(o.y);
        o.z = accF[j].z/dh + bb.z;  o.z = (o.z > 0.f) ? o.z : expm1f(o.z);
        o.w = accF[j].w/dh + bb.w;  o.w = (o.w > 0.f) ? o.w : expm1f(o.w);
        *(float4*)&out[(long)v*CH + j*128 + 4*lane] = o;
    }
    if (HASREM) {
        float dh = __shfl_sync(0xffffffffu, den, headR);
        float2 bb = *(const float2*)&bias[NFULL*128 + 2*lane];
        float2 o;
        o.x = accR.x/dh + bb.x;  o.x = (o.x > 0.f) ? o.x : expm1f(o.x);
        o.y = accR.y/dh + bb.y;  o.y = (o.y > 0.f) ? o.y : expm1f(o.y);
        *(float2*)&out[(long)v*CH + NFULL*128 + 2*lane] = o;
    }
}

// ---------------- pair head ----------------
__global__ void pair_kernel(const float* __restrict__ x2,
                            const int* __restrict__ n1,
                            const int* __restrict__ n2,
                            const float* __restrict__ linW,
                            const float* __restrict__ linb,
                            float* __restrict__ y, int P)
{
    int p = blockIdx.x*blockDim.x + threadIdx.x;
    if (p >= P) return;
    const float* a  = x2 + (long)n1[p]*CH2;
    const float* bb = x2 + (long)n2[p]*CH2;
    float y0 = linb[0], y1 = linb[1];
    #pragma unroll
    for (int j = 0; j < CH2; j++) {
        float v = a[j];
        y0 = fmaf(v, linW[j*2],   y0);
        y1 = fmaf(v, linW[j*2+1], y1);
    }
    #pragma unroll
    for (int j = 0; j < CH2; j++) {
        float v = bb[j];
        y0 = fmaf(v, linW[(CH2+j)*2],   y0);
        y1 = fmaf(v, linW[(CH2+j)*2+1], y1);
    }
    y[p*2]   = 1.f/(1.f + __expf(-y0));
    y[p*2+1] = 1.f/(1.f + __expf(-y1));
}

// ---------------- launch ----------------
extern "C" void kernel_launch(void* const* d_in, const int* in_sizes, int n_in,
                              void* d_out, int out_size)
{
    const float* features = (const float*)d_in[0];
    const int*   eidx     = (const int*)  d_in[1];
    const int*   n1idx    = (const int*)  d_in[2];
    const int*   n2idx    = (const int*)  d_in[3];
    const float* W1       = (const float*)d_in[4];
    const float* attS1    = (const float*)d_in[5];
    const float* attD1    = (const float*)d_in[6];
    const float* b1       = (const float*)d_in[7];
    const float* W2       = (const float*)d_in[8];
    const float* attS2    = (const float*)d_in[9];
    const float* attD2    = (const float*)d_in[10];
    const float* b2       = (const float*)d_in[11];
    const float* linW     = (const float*)d_in[12];
    const float* linb     = (const float*)d_in[13];

    const int N = N_NODES;
    const int E = in_sizes[1] / 2;
    const int P = in_sizes[2];
    const int etot = E + N;
    const int* srcE = eidx;
    const int* dstE = eidx + E;

    float* y_out  = (float*)d_out;          // [P,2]
    float* x2_out = y_out + (long)P*2;      // [N,64]

    float *p_h1, *p_x1, *p_h2, *p_as1, *p_ad1, *p_as2, *p_ad2;
    cudaGetSymbolAddress((void**)&p_h1,  g_h1);
    cudaGetSymbolAddress((void**)&p_x1,  g_x1);
    cudaGetSymbolAddress((void**)&p_h2,  g_h2);
    cudaGetSymbolAddress((void**)&p_as1, g_as1);
    cudaGetSymbolAddress((void**)&p_ad1, g_ad1);
    cudaGetSymbolAddress((void**)&p_as2, g_as2);
    cudaGetSymbolAddress((void**)&p_ad2, g_ad2);

    // ---- CSR build; gemm1 kept as 4th launch for the ncu sample ----
    zero_kernel<<<(N+255)/256, 256>>>(N);
    count_kernel<<<(etot+255)/256, 256>>>(dstE, E, N);
    int nb = (N + 1023) / 1024;
    scan1_kernel<<<nb, 1024>>>(N);
    {
        dim3 grid((N + 127)/128, CH1/96);
        gemm_tc_kernel<96><<<grid, 256>>>(features, W1, p_h1, N, CH1, NUM_FEA);
    }
    scan2_kernel<<<1, 64>>>(nb);
    scan3_kernel<<<(N+255)/256, 256>>>(N);
    scatter_kernel<<<(etot+255)/256, 256>>>(srcE, dstE, E, N);

    // ---- layer 1 ----
    attn_kernel<HEAD1, HID1><<<(N*HEAD1 + 255)/256, 256>>>(p_h1, attS1, attD1, p_as1, p_ad1, N);
    agg_kernel<HEAD1, HID1><<<(N*32 + 255)/256, 256>>>(p_h1, p_as1, p_ad1, b1, p_x1, N);

    // ---- layer 2 ----
    {
        dim3 grid((N + 127)/128, 1);
        gemm_tc_kernel<64><<<grid, 256>>>(p_x1, W2, p_h2, N, CH2, CH1);
    }
    attn_kernel<HEAD2, HID2><<<(N*HEAD2 + 255)/256, 256>>>(p_h2, attS2, attD2, p_as2, p_ad2, N);
    agg_kernel<HEAD2, HID2><<<(N*32 + 255)/256, 256>>>(p_h2, p_as2, p_ad2, b2, x2_out, N);

    // ---- pair head ----
    pair_kernel<<<(P+255)/256, 256>>>(x2_out, n1idx, n2idx, linW, linb, y_out, P);
}